// round 11
// baseline (speedup 1.0000x reference)
#include <cuda_runtime.h>
#include <cuda_fp16.h>
#include <math.h>
#include <stdint.h>

#define B_  2
#define S_  2048
#define D_  1024
#define V_  32000
#define NL_ 6
#define M_  (B_*S_)   // 4096 tokens

// ---------------------------------------------------------------------------
// Scratch
// ---------------------------------------------------------------------------
__device__ float  g_x0[M_*D_];
__device__ float  g_x1[M_*D_];
__device__ float  g_hT[M_*D_];
__device__ float2 g_stats[M_];

__device__ __half g_x016[M_*D_], g_x116[M_*D_];
__device__ __half g_yT16[M_*D_];                       // conv out, (B,D,S) fp16
__device__ __half g_wr16[NL_*D_*D_];
__device__ __half g_wg16[NL_*D_*D_];
__device__ __half g_xf16[M_*D_];
__device__ __half g_wo16[(size_t)V_*D_];

// ---------------------------------------------------------------------------
// PTX helpers
// ---------------------------------------------------------------------------
__device__ __forceinline__ uint32_t smem_u32(const void* p) {
    uint32_t a;
    asm("{ .reg .u64 t; cvta.to.shared.u64 t, %1; cvt.u32.u64 %0, t; }" : "=r"(a) : "l"(p));
    return a;
}
__device__ __forceinline__ void cp16s(uint32_t saddr, const void* g) {
    asm volatile("cp.async.cg.shared.global [%0], [%1], 16;\n" :: "r"(saddr), "l"(g));
}
__device__ __forceinline__ void cp_commit() {
    asm volatile("cp.async.commit_group;\n" ::: "memory");
}
template<int N_> __device__ __forceinline__ void cp_wait() {
    asm volatile("cp.async.wait_group %0;\n" :: "n"(N_) : "memory");
}
__device__ __forceinline__ void mma_fp16(float* c, const uint32_t* a, const uint32_t* b) {
    asm volatile(
        "mma.sync.aligned.m16n8k16.row.col.f32.f16.f16.f32 "
        "{%0,%1,%2,%3}, {%4,%5,%6,%7}, {%8,%9}, {%0,%1,%2,%3};"
        : "+f"(c[0]), "+f"(c[1]), "+f"(c[2]), "+f"(c[3])
        : "r"(a[0]), "r"(a[1]), "r"(a[2]), "r"(a[3]), "r"(b[0]), "r"(b[1]));
}
#define LDSM4(r0, r1, r2, r3, addr) \
    asm volatile("ldmatrix.sync.aligned.m8n8.x4.shared.b16 {%0,%1,%2,%3}, [%4];" \
        : "=r"(r0), "=r"(r1), "=r"(r2), "=r"(r3) : "r"(addr))
#define LDSM4T(r0, r1, r2, r3, addr) \
    asm volatile("ldmatrix.sync.aligned.m8n8.x4.trans.shared.b16 {%0,%1,%2,%3}, [%4];" \
        : "=r"(r0), "=r"(r1), "=r"(r2), "=r"(r3) : "r"(addr))

#define RSTR   48                    // bytes per smem row (token-major tiles)
#define TILE_B (128 * RSTR)          // 6144 B per 128x16 fp16 tile
#define ARSTR   272                  // A^T tile row stride (trans ldmatrix)
#define ATILE_B (16 * ARSTR)         // 4352 B

// ---------------------------------------------------------------------------
// Merged layer kernel: BOTH per-layer GEMMs in one K-loop + fused combine.
//   zR = yT16^T * Wr   (A via trans-ldmatrix from (B,D,S) conv output)
//   zG = cur16  * Wg   (token-major A)
//   s = sigmoid(zG + gb);  x' = s*(zR + rb) + (1-s)*orig  -> fp32 + fp16
// CTA 128x128, BK=16, 8 warps (64x32), 3-stage cp.async, occupancy 1.
// ---------------------------------------------------------------------------
#define LSTAGE_B (ATILE_B + 3 * TILE_B)      // 22784 B per stage
#define LGEMM_SMEM (3 * LSTAGE_B)            // 68352 B

__global__ void __launch_bounds__(256, 1) gemm_layer(
        const __half* __restrict__ AT,       // yT16 (B,D,S)
        const __half* __restrict__ A2,       // cur16 (M,K)
        const __half* __restrict__ B1,       // wr16 [N][K]
        const __half* __restrict__ B2,       // wg16 [N][K]
        const float* __restrict__ rbias,
        const float* __restrict__ gbias,
        const float* __restrict__ orig,      // cur fp32 (M,N)
        float* __restrict__ Cout, __half* __restrict__ C16,
        int N, int K)
{
    extern __shared__ char smem[];
    uint32_t sb = smem_u32(smem);

    int tid  = threadIdx.x;
    int lane = tid & 31;
    int warp = tid >> 5;
    int g = lane >> 2, t = lane & 3;
    int wm = (warp >> 2) * 64;
    int wn = (warp & 3) * 32;
    int m0 = blockIdx.x * 128, n0 = blockIdx.y * 128;
    int bz = m0 / S_;
    int sm0 = m0 & (S_ - 1);

    uint32_t aoffT = (uint32_t)((((lane & 7) + ((lane >> 4) & 1) * 8) * ARSTR) + ((lane >> 3) & 1) * 16);
    uint32_t aoff  = (uint32_t)((((lane & 7) + ((lane >> 3) & 1) * 8) * RSTR) + ((lane >> 4) & 1) * 16);
    uint32_t boff  = (uint32_t)((((lane & 7) + ((lane >> 4) & 1) * 8) * RSTR) + ((lane >> 3) & 1) * 16);

    int ar = tid >> 4, ac = tid & 15;        // A^T: 16 rows x 16 chunks
    int lr = tid >> 1;                       // token-major: 128 rows x 2 chunks
    uint32_t aso = (uint32_t)(ar * ARSTR + ac * 16);
    uint32_t bso = (uint32_t)(lr * RSTR + (tid & 1) * 16);
    int lc8 = (tid & 1) * 8;

    float accR[4][4][4], accG[4][4][4];
#pragma unroll
    for (int mi = 0; mi < 4; mi++)
#pragma unroll
        for (int ni = 0; ni < 4; ni++)
#pragma unroll
            for (int r = 0; r < 4; r++) { accR[mi][ni][r] = 0.f; accG[mi][ni][r] = 0.f; }

    auto load_stage = [&](int st, int kt) {
        int k0 = kt * 16;
        uint32_t base = sb + (uint32_t)st * LSTAGE_B;
        cp16s(base + aso, AT + (size_t)(bz * D_ + k0 + ar) * S_ + sm0 + ac * 8);
        size_t gt = (size_t)(m0 + lr) * K + k0 + lc8;
        size_t gb = (size_t)(n0 + lr) * K + k0 + lc8;
        cp16s(base + ATILE_B + bso,              A2 + gt);
        cp16s(base + ATILE_B + TILE_B + bso,     B1 + gb);
        cp16s(base + ATILE_B + 2 * TILE_B + bso, B2 + gb);
    };

    int KT = K >> 4;
    load_stage(0, 0); cp_commit();
    load_stage(1, 1); cp_commit();

    for (int kt = 0; kt < KT; kt++) {
        if (kt == KT - 1) cp_wait<0>(); else cp_wait<1>();
        __syncthreads();
        if (kt + 2 < KT) { load_stage((kt + 2) % 3, kt + 2); cp_commit(); }

        uint32_t base = sb + (uint32_t)(kt % 3) * LSTAGE_B;
        uint32_t tA  = base;
        uint32_t tC  = base + ATILE_B;
        uint32_t tB1 = tC + TILE_B;
        uint32_t tB2 = tB1 + TILE_B;

        uint32_t af[16], bf[8];

        // --- refine half: A from trans tile, B = Wr ---
        LDSM4(bf[0], bf[1], bf[2], bf[3], tB1 + (uint32_t)(wn * RSTR) + boff);
        LDSM4(bf[4], bf[5], bf[6], bf[7], tB1 + (uint32_t)((wn + 16) * RSTR) + boff);
#pragma unroll
        for (int mi = 0; mi < 4; mi++)
            LDSM4T(af[mi*4], af[mi*4+1], af[mi*4+2], af[mi*4+3],
                   tA + aoffT + (uint32_t)((wm + mi * 16) * 2));
#pragma unroll
        for (int mi = 0; mi < 4; mi++)
#pragma unroll
            for (int ni = 0; ni < 4; ni++)
                mma_fp16(accR[mi][ni], &af[mi*4], &bf[ni*2]);

        // --- gate half: A = cur16 token-major, B = Wg ---
        LDSM4(bf[0], bf[1], bf[2], bf[3], tB2 + (uint32_t)(wn * RSTR) + boff);
        LDSM4(bf[4], bf[5], bf[6], bf[7], tB2 + (uint32_t)((wn + 16) * RSTR) + boff);
#pragma unroll
        for (int mi = 0; mi < 4; mi++)
            LDSM4(af[mi*4], af[mi*4+1], af[mi*4+2], af[mi*4+3],
                  tC + (uint32_t)((wm + mi * 16) * RSTR) + aoff);
#pragma unroll
        for (int mi = 0; mi < 4; mi++)
#pragma unroll
            for (int ni = 0; ni < 4; ni++)
                mma_fp16(accG[mi][ni], &af[mi*4], &bf[ni*2]);
    }

    // Fused combine epilogue
#pragma unroll
    for (int mi = 0; mi < 4; mi++) {
        int r0 = m0 + wm + mi * 16 + g;
#pragma unroll
        for (int ni = 0; ni < 4; ni++) {
            int c0 = n0 + wn + ni * 8 + t * 2;
            float rb0 = rbias[c0], rb1 = rbias[c0 + 1];
            float gb0 = gbias[c0], gb1 = gbias[c0 + 1];
            size_t o0 = (size_t)r0 * N + c0;
            size_t o1 = (size_t)(r0 + 8) * N + c0;
            float* aR = accR[mi][ni];
            float* aG = accG[mi][ni];
            float zR[4]  = {aR[0] + rb0, aR[1] + rb1, aR[2] + rb0, aR[3] + rb1};
            float zG[4]  = {aG[0] + gb0, aG[1] + gb1, aG[2] + gb0, aG[3] + gb1};
            size_t offs[4] = {o0, o0 + 1, o1, o1 + 1};
#pragma unroll
            for (int j = 0; j < 4; j++) {
                float gt = 1.f / (1.f + expf(-zG[j]));
                float res = gt * zR[j] + (1.f - gt) * orig[offs[j]];
                Cout[offs[j]] = res;
                C16[offs[j]] = __float2half(res);
            }
        }
    }
}

// ---------------------------------------------------------------------------
// Output GEMM: single-product fp16, token-major A. C = A*B + bias (fp32).
// ---------------------------------------------------------------------------
#define OSTAGE_B (2 * TILE_B)          // 12288 B
#define OGEMM_SMEM (3 * OSTAGE_B)      // 36864 B

__global__ void __launch_bounds__(256, 2) gemm_out(
        const __half* __restrict__ A, const __half* __restrict__ Bm,
        const float* __restrict__ bias,
        float* __restrict__ C, int M, int N, int K)
{
    extern __shared__ char smem[];
    uint32_t sb = smem_u32(smem);

    int tid  = threadIdx.x;
    int lane = tid & 31;
    int warp = tid >> 5;
    int g = lane >> 2, t = lane & 3;
    int wm = (warp >> 2) * 64;
    int wn = (warp & 3) * 32;
    int m0 = blockIdx.x * 128, n0 = blockIdx.y * 128;

    uint32_t aoff = (uint32_t)((((lane & 7) + ((lane >> 3) & 1) * 8) * RSTR) + ((lane >> 4) & 1) * 16);
    uint32_t boff = (uint32_t)((((lane & 7) + ((lane >> 4) & 1) * 8) * RSTR) + ((lane >> 3) & 1) * 16);

    int lr = tid >> 1;
    int lc8 = (tid & 1) * 8;
    uint32_t so = (uint32_t)(lr * RSTR + (tid & 1) * 16);

    float acc[4][4][4];
#pragma unroll
    for (int mi = 0; mi < 4; mi++)
#pragma unroll
        for (int ni = 0; ni < 4; ni++)
#pragma unroll
            for (int r = 0; r < 4; r++) acc[mi][ni][r] = 0.f;

    auto load_stage = [&](int st, int kt) {
        int k0 = kt * 16;
        uint32_t base = sb + (uint32_t)st * OSTAGE_B;
        cp16s(base + so,          A  + (size_t)(m0 + lr) * K + k0 + lc8);
        cp16s(base + TILE_B + so, Bm + (size_t)(n0 + lr) * K + k0 + lc8);
    };

    int KT = K >> 4;
    load_stage(0, 0); cp_commit();
    load_stage(1, 1); cp_commit();

    for (int kt = 0; kt < KT; kt++) {
        if (kt == KT - 1) cp_wait<0>(); else cp_wait<1>();
        __syncthreads();
        if (kt + 2 < KT) { load_stage((kt + 2) % 3, kt + 2); cp_commit(); }

        uint32_t base = sb + (uint32_t)(kt % 3) * OSTAGE_B;
        uint32_t tA = base, tB = base + TILE_B;

        uint32_t af[16], bf[8];
        LDSM4(bf[0], bf[1], bf[2], bf[3], tB + (uint32_t)(wn * RSTR) + boff);
        LDSM4(bf[4], bf[5], bf[6], bf[7], tB + (uint32_t)((wn + 16) * RSTR) + boff);
#pragma unroll
        for (int mi = 0; mi < 4; mi++)
            LDSM4(af[mi*4], af[mi*4+1], af[mi*4+2], af[mi*4+3],
                  tA + (uint32_t)((wm + mi * 16) * RSTR) + aoff);
#pragma unroll
        for (int mi = 0; mi < 4; mi++)
#pragma unroll
            for (int ni = 0; ni < 4; ni++)
                mma_fp16(acc[mi][ni], &af[mi*4], &bf[ni*2]);
    }

#pragma unroll
    for (int mi = 0; mi < 4; mi++) {
        int r0 = m0 + wm + mi * 16 + g;
#pragma unroll
        for (int ni = 0; ni < 4; ni++) {
            int c0 = n0 + wn + ni * 8 + t * 2;
            float bv0 = bias[c0], bv1 = bias[c0 + 1];
            size_t o0 = (size_t)r0 * N + c0;
            size_t o1 = (size_t)(r0 + 8) * N + c0;
            float* a4 = acc[mi][ni];
            C[o0]     = a4[0] + bv0;
            C[o0 + 1] = a4[1] + bv1;
            C[o1]     = a4[2] + bv0;
            C[o1 + 1] = a4[3] + bv1;
        }
    }
}

// ---------------------------------------------------------------------------
// Embedding + sinusoidal PE (+ fp16 copy for layer-0 gate A)
// ---------------------------------------------------------------------------
__global__ void embed_kernel(const int* __restrict__ ids,
                             const float* __restrict__ emb,
                             float* __restrict__ x,
                             __half* __restrict__ x16) {
    int row = blockIdx.x;
    int s   = row & (S_ - 1);
    int tok = ids[row];
    int d0  = threadIdx.x * 4;
    float4 e = *(const float4*)(emb + (size_t)tok * D_ + d0);
    const float cln = -logf(10000.0f) / (float)D_;
    float pe[4];
#pragma unroll
    for (int j = 0; j < 4; j += 2) {
        float freq = expf(cln * (float)(d0 + j));
        float a = (float)s * freq;
        pe[j]   = sinf(a);
        pe[j+1] = cosf(a);
    }
    float o[4] = {e.x + pe[0], e.y + pe[1], e.z + pe[2], e.w + pe[3]};
    *(float4*)(x + (size_t)row * D_ + d0) = *(float4*)o;
    __half2 p0 = __floats2half2_rn(o[0], o[1]);
    __half2 p1 = __floats2half2_rn(o[2], o[3]);
    uint2 packed = {*(uint32_t*)&p0, *(uint32_t*)&p1};
    *(uint2*)(x16 + (size_t)row * D_ + d0) = packed;
}

// ---------------------------------------------------------------------------
// fp16 convert (layer weights)
// ---------------------------------------------------------------------------
__global__ void conv16_kernel(const float* __restrict__ w,
                              __half* __restrict__ o, int n4) {
    int i = blockIdx.x * 256 + threadIdx.x;
    if (i >= n4) return;
    float4 v = ((const float4*)w)[i];
    __half2 p0 = __floats2half2_rn(v.x, v.y);
    __half2 p1 = __floats2half2_rn(v.z, v.w);
    uint2 packed = {*(uint32_t*)&p0, *(uint32_t*)&p1};
    ((uint2*)o)[i] = packed;
}

// ---------------------------------------------------------------------------
// outW (D,V) -> [V][D] fp16
// ---------------------------------------------------------------------------
__global__ void wout_t16_kernel(const float* __restrict__ w,
                                __half* __restrict__ o16) {
    __shared__ float tile[32][33];
    int v0 = blockIdx.x * 32, d0 = blockIdx.y * 32;
    int tx = threadIdx.x, ty = threadIdx.y;
#pragma unroll
    for (int i = 0; i < 4; i++)
        tile[ty + i * 8][tx] = w[(size_t)(d0 + ty + i * 8) * V_ + v0 + tx];
    __syncthreads();
#pragma unroll
    for (int i = 0; i < 4; i++) {
        size_t o = (size_t)(v0 + ty + i * 8) * D_ + d0 + tx;
        o16[o] = __float2half(tile[tx][ty + i * 8]);
    }
}

// ---------------------------------------------------------------------------
// LayerNorm statistics
// ---------------------------------------------------------------------------
__global__ void ln_stats_kernel(const float* __restrict__ x, float2* __restrict__ stats) {
    int row = blockIdx.x;
    float4 v = ((const float4*)(x + (size_t)row * D_))[threadIdx.x];
    float s = v.x + v.y + v.z + v.w;
    float q = v.x*v.x + v.y*v.y + v.z*v.z + v.w*v.w;
#pragma unroll
    for (int o = 16; o; o >>= 1) {
        s += __shfl_xor_sync(0xffffffffu, s, o);
        q += __shfl_xor_sync(0xffffffffu, q, o);
    }
    __shared__ float ss[8], sq[8];
    int w = threadIdx.x >> 5;
    if ((threadIdx.x & 31) == 0) { ss[w] = s; sq[w] = q; }
    __syncthreads();
    if (threadIdx.x == 0) {
        float S = 0.f, Q = 0.f;
#pragma unroll
        for (int i = 0; i < 8; i++) { S += ss[i]; Q += sq[i]; }
        float mu  = S / (float)D_;
        float var = Q / (float)D_ - mu * mu;
        stats[row] = make_float2(mu, rsqrtf(var + 1e-5f));
    }
}

// ---------------------------------------------------------------------------
// Apply LN while transposing (B,S,D)->(B,D,S)
// ---------------------------------------------------------------------------
__global__ void ln_transpose_kernel(const float* __restrict__ x,
                                    const float2* __restrict__ stats,
                                    const float* __restrict__ g,
                                    const float* __restrict__ bta,
                                    float* __restrict__ hT) {
    __shared__ float tile[32][33];
    int b  = blockIdx.z;
    int s0 = blockIdx.x * 32, d0 = blockIdx.y * 32;
    int tx = threadIdx.x, ty = threadIdx.y;
    float gg = g[d0 + tx], bb = bta[d0 + tx];
#pragma unroll
    for (int i = 0; i < 4; i++) {
        int s = s0 + ty + i * 8;
        float2 st = stats[b * S_ + s];
        float v = x[((size_t)(b * S_ + s)) * D_ + d0 + tx];
        tile[ty + i * 8][tx] = (v - st.x) * st.y * gg + bb;
    }
    __syncthreads();
#pragma unroll
    for (int i = 0; i < 4; i++) {
        int d = d0 + ty + i * 8;
        hT[((size_t)(b * D_ + d)) * S_ + s0 + tx] = tile[tx][ty + i * 8];
    }
}

// ---------------------------------------------------------------------------
// Final LN apply -> fp16
// ---------------------------------------------------------------------------
__global__ void apply_ln_kernel(const float* __restrict__ x,
                                const float2* __restrict__ stats,
                                const float* __restrict__ g,
                                const float* __restrict__ b,
                                __half* __restrict__ o16) {
    int row = blockIdx.x;
    int d0 = threadIdx.x * 4;
    float2 st = stats[row];
    float4 v  = *(const float4*)(x + (size_t)row * D_ + d0);
    float4 gg = *(const float4*)(g + d0);
    float4 bb = *(const float4*)(b + d0);
    __half2 p0 = __floats2half2_rn((v.x - st.x) * st.y * gg.x + bb.x,
                                   (v.y - st.x) * st.y * gg.y + bb.y);
    __half2 p1 = __floats2half2_rn((v.z - st.x) * st.y * gg.z + bb.z,
                                   (v.w - st.x) * st.y * gg.w + bb.w);
    uint2 packed = {*(uint32_t*)&p0, *(uint32_t*)&p1};
    *(uint2*)(o16 + (size_t)row * D_ + d0) = packed;
}

// ---------------------------------------------------------------------------
// Depthwise conv chain per (b,d) channel -> fp16 (B,D,S) output.
// ---------------------------------------------------------------------------
__global__ void __launch_bounds__(256) conv_kernel(const float* __restrict__ hT,
                                                   const float* __restrict__ lw,
                                                   const float* __restrict__ fw,
                                                   const float* __restrict__ mw,
                                                   __half* __restrict__ yT16) {
    int bd = blockIdx.x;
    int d  = bd & (D_ - 1);
    __shared__ float bufA[S_ + 64];
    __shared__ float bufB[S_ + 64];
    __shared__ float w3[3], wA[64], wB[64];
    int tid = threadIdx.x;
    if (tid < 64) {
        wA[tid] = fw[(size_t)d * 64 + tid];
        wB[tid] = fw[(size_t)(D_ + d) * 64 + tid];
    }
    if (tid < 3) w3[tid] = lw[d * 3 + tid];
    if (tid < 32) {
        bufA[tid] = 0.f; bufA[S_ + 32 + tid] = 0.f;
        bufB[tid] = 0.f; bufB[S_ + 32 + tid] = 0.f;
    }
    const float* cin = hT + (size_t)bd * S_;
    for (int i = tid; i < S_ / 4; i += 256)
        ((float4*)(bufA + 32))[i] = ((const float4*)cin)[i];
    __syncthreads();
    for (int s = tid; s < S_; s += 256)
        bufB[32 + s] = bufA[31 + s] * w3[0] + bufA[32 + s] * w3[1] + bufA[33 + s] * w3[2];
    __syncthreads();

    int s0 = tid * 8;
    float acc[8], win[8], nxt[8];

#pragma unroll
    for (int j = 0; j < 8; j++) { acc[j] = bufA[32 + s0 + j]; win[j] = bufB[s0 + j]; }
#pragma unroll
    for (int k0 = 0; k0 < 64; k0 += 8) {
#pragma unroll
        for (int j = 0; j < 8; j++) nxt[j] = bufB[s0 + 8 + k0 + j];
#pragma unroll
        for (int kk = 0; kk < 8; kk++) {
            float wk = wA[k0 + kk];
#pragma unroll
            for (int j = 0; j < 8; j++) {
                int ix = j + kk;
                acc[j] += (ix < 8 ? win[ix] : nxt[ix - 8]) * wk;
            }
        }
#pragma unroll
        for (int j = 0; j < 8; j++) win[j] = nxt[j];
    }
    __syncthreads();
#pragma unroll
    for (int j = 0; j < 8; j++) bufA[32 + s0 + j] = acc[j];
    __syncthreads();

    float mwd = mw[d];
#pragma unroll
    for (int j = 0; j < 8; j++) { acc[j] = 0.f; win[j] = bufA[s0 + j]; }
#pragma unroll
    for (int k0 = 0; k0 < 64; k0 += 8) {
#pragma unroll
        for (int j = 0; j < 8; j++) nxt[j] = bufA[s0 + 8 + k0 + j];
#pragma unroll
        for (int kk = 0; kk < 8; kk++) {
            float wk = wB[k0 + kk];
#pragma unroll
            for (int j = 0; j < 8; j++) {
                int ix = j + kk;
                acc[j] += (ix < 8 ? win[ix] : nxt[ix - 8]) * wk;
            }
        }
#pragma unroll
        for (int j = 0; j < 8; j++) win[j] = nxt[j];
    }
    __half hv[8];
#pragma unroll
    for (int j = 0; j < 8; j++) {
        float m = acc[j] * mwd;
        hv[j] = __float2half(m / (1.0f + expf(-m)));
    }
    *(uint4*)(yT16 + (size_t)bd * S_ + s0) = *(uint4*)hv;
}

// ---------------------------------------------------------------------------
// Host orchestration
// ---------------------------------------------------------------------------
static void* sym_addr(const void* sym) {
    void* p = nullptr;
    cudaGetSymbolAddress(&p, sym);
    return p;
}

extern "C" void kernel_launch(void* const* d_in, const int* in_sizes, int n_in,
                              void* d_out, int out_size) {
    (void)in_sizes; (void)n_in; (void)out_size;
    const int*   ids   = (const int*)d_in[0];
    const float* emb   = (const float*)d_in[1];
    const float* lw    = (const float*)d_in[2];
    const float* fw    = (const float*)d_in[3];
    const float* mw    = (const float*)d_in[4];
    const float* ln1g  = (const float*)d_in[5];
    const float* ln1b  = (const float*)d_in[6];
    const float* refW  = (const float*)d_in[7];
    const float* refb  = (const float*)d_in[8];
    const float* gateW = (const float*)d_in[9];
    const float* gateb = (const float*)d_in[10];
    const float* lnfg  = (const float*)d_in[11];
    const float* lnfb  = (const float*)d_in[12];
    const float* outW  = (const float*)d_in[13];
    const float* outb  = (const float*)d_in[14];
    float* out = (float*)d_out;

    float*  x0  = (float*)sym_addr(g_x0);
    float*  x1  = (float*)sym_addr(g_x1);
    float*  hT  = (float*)sym_addr(g_hT);
    float2* st  = (float2*)sym_addr(g_stats);
    __half* x016 = (__half*)sym_addr(g_x016);
    __half* x116 = (__half*)sym_addr(g_x116);
    __half* yT16 = (__half*)sym_addr(g_yT16);
    __half* wr16 = (__half*)sym_addr(g_wr16);
    __half* wg16 = (__half*)sym_addr(g_wg16);
    __half* xf16 = (__half*)sym_addr(g_xf16);
    __half* wo16 = (__half*)sym_addr(g_wo16);

    cudaFuncSetAttribute(gemm_layer, cudaFuncAttributeMaxDynamicSharedMemorySize, LGEMM_SMEM);
    cudaFuncSetAttribute(gemm_out,   cudaFuncAttributeMaxDynamicSharedMemorySize, OGEMM_SMEM);

    {
        int n4 = NL_ * D_ * D_ / 4;
        conv16_kernel<<<(n4 + 255) / 256, 256>>>(refW,  wr16, n4);
        conv16_kernel<<<(n4 + 255) / 256, 256>>>(gateW, wg16, n4);
        wout_t16_kernel<<<dim3(V_ / 32, D_ / 32), dim3(32, 8)>>>(outW, wo16);
    }

    embed_kernel<<<M_, 256>>>(ids, emb, x0, x016);

    float* cur = x0;        float* nxt = x1;
    __half *cur16 = x016, *nxt16 = x116;
    for (int l = 0; l < NL_; l++) {
        ln_stats_kernel<<<M_, 256>>>(cur, st);
        ln_transpose_kernel<<<dim3(S_/32, D_/32, B_), dim3(32, 8)>>>(
            cur, st, ln1g + (size_t)l * D_, ln1b + (size_t)l * D_, hT);
        conv_kernel<<<B_*D_, 256>>>(
            hT, lw + (size_t)l * D_ * 3, fw + (size_t)l * 2 * D_ * 64,
            mw + (size_t)l * D_, yT16);
        gemm_layer<<<dim3(M_/128, D_/128), 256, LGEMM_SMEM>>>(
            yT16, cur16,
            wr16 + (size_t)l * D_ * D_, wg16 + (size_t)l * D_ * D_,
            refb + (size_t)l * D_, gateb + (size_t)l * D_,
            cur, nxt, nxt16, D_, D_);
        { float* tf = cur; cur = nxt; nxt = tf; }
        { __half* th = cur16; cur16 = nxt16; nxt16 = th; }
    }

    ln_stats_kernel<<<M_, 256>>>(cur, st);
    apply_ln_kernel<<<M_, 256>>>(cur, st, lnfg, lnfb, xf16);
    gemm_out<<<dim3(M_/128, V_/128), 256, OGEMM_SMEM>>>(
        xf16, wo16, outb, out, M_, V_, D_);
}

// round 12
// speedup vs baseline: 1.0227x; 1.0227x over previous
#include <cuda_runtime.h>
#include <cuda_fp16.h>
#include <math.h>
#include <stdint.h>

#define B_  2
#define S_  2048
#define D_  1024
#define V_  32000
#define NL_ 6
#define M_  (B_*S_)   // 4096 tokens

// ---------------------------------------------------------------------------
// Scratch
// ---------------------------------------------------------------------------
__device__ float  g_x0[M_*D_];
__device__ float  g_x1[M_*D_];
__device__ float  g_hT[M_*D_];
__device__ float2 g_stats[M_];

__device__ __half g_x016[M_*D_], g_x116[M_*D_];
__device__ __half g_yT16[M_*D_];                       // conv out, (B,D,S) fp16
__device__ __half g_wr16[NL_*D_*D_];
__device__ __half g_wg16[NL_*D_*D_];
__device__ __half g_xf16[M_*D_];
__device__ __half g_wo16[(size_t)V_*D_];

// ---------------------------------------------------------------------------
// PTX helpers
// ---------------------------------------------------------------------------
__device__ __forceinline__ uint32_t smem_u32(const void* p) {
    uint32_t a;
    asm("{ .reg .u64 t; cvta.to.shared.u64 t, %1; cvt.u32.u64 %0, t; }" : "=r"(a) : "l"(p));
    return a;
}
__device__ __forceinline__ void cp16s(uint32_t saddr, const void* g) {
    asm volatile("cp.async.cg.shared.global [%0], [%1], 16;\n" :: "r"(saddr), "l"(g));
}
__device__ __forceinline__ void cp_commit() {
    asm volatile("cp.async.commit_group;\n" ::: "memory");
}
template<int N_> __device__ __forceinline__ void cp_wait() {
    asm volatile("cp.async.wait_group %0;\n" :: "n"(N_) : "memory");
}
__device__ __forceinline__ void mma_fp16(float* c, const uint32_t* a, const uint32_t* b) {
    asm volatile(
        "mma.sync.aligned.m16n8k16.row.col.f32.f16.f16.f32 "
        "{%0,%1,%2,%3}, {%4,%5,%6,%7}, {%8,%9}, {%0,%1,%2,%3};"
        : "+f"(c[0]), "+f"(c[1]), "+f"(c[2]), "+f"(c[3])
        : "r"(a[0]), "r"(a[1]), "r"(a[2]), "r"(a[3]), "r"(b[0]), "r"(b[1]));
}
#define LDSM4(r0, r1, r2, r3, addr) \
    asm volatile("ldmatrix.sync.aligned.m8n8.x4.shared.b16 {%0,%1,%2,%3}, [%4];" \
        : "=r"(r0), "=r"(r1), "=r"(r2), "=r"(r3) : "r"(addr))
#define LDSM4T(r0, r1, r2, r3, addr) \
    asm volatile("ldmatrix.sync.aligned.m8n8.x4.trans.shared.b16 {%0,%1,%2,%3}, [%4];" \
        : "=r"(r0), "=r"(r1), "=r"(r2), "=r"(r3) : "r"(addr))

#define RSTR   48                    // bytes per smem row (token-major tiles)
#define TILE_B (128 * RSTR)          // 6144 B per 128x16 fp16 tile
#define ARSTR   272                  // A^T tile row stride (trans ldmatrix)
#define ATILE_B (16 * ARSTR)         // 4352 B

// ---------------------------------------------------------------------------
// Merged layer kernel (512 threads, 16 warps, 32x32 warp tiles -> occ regs OK,
// 16 resident warps = same latency hiding as 2x256-thread CTAs).
//   zR = yT16^T * Wr   (trans-ldmatrix from (B,D,S) conv output)
//   zG = cur16  * Wg   (token-major)
//   s = sigmoid(zG+gb);  x' = s*(zR+rb) + (1-s)*orig  -> fp32 + fp16
// CTA tile 128x128, BK=16, 3-stage cp.async.
// ---------------------------------------------------------------------------
#define LSTAGE_B (ATILE_B + 3 * TILE_B)      // 22784 B per stage
#define LGEMM_SMEM (3 * LSTAGE_B)            // 68352 B

__global__ void __launch_bounds__(512, 1) gemm_layer(
        const __half* __restrict__ AT,       // yT16 (B,D,S)
        const __half* __restrict__ A2,       // cur16 (M,K)
        const __half* __restrict__ B1,       // wr16 [N][K]
        const __half* __restrict__ B2,       // wg16 [N][K]
        const float* __restrict__ rbias,
        const float* __restrict__ gbias,
        const float* __restrict__ orig,      // cur fp32 (M,N)
        float* __restrict__ Cout, __half* __restrict__ C16,
        int N, int K)
{
    extern __shared__ char smem[];
    uint32_t sb = smem_u32(smem);

    int tid  = threadIdx.x;
    int lane = tid & 31;
    int warp = tid >> 5;                 // 0..15
    int g = lane >> 2, t = lane & 3;
    int wm = (warp >> 2) * 32;           // 0,32,64,96
    int wn = (warp & 3) * 32;            // 0,32,64,96
    int m0 = blockIdx.x * 128, n0 = blockIdx.y * 128;
    int bz = m0 / S_;
    int sm0 = m0 & (S_ - 1);

    uint32_t aoffT = (uint32_t)((((lane & 7) + ((lane >> 4) & 1) * 8) * ARSTR) + ((lane >> 3) & 1) * 16);
    uint32_t aoff  = (uint32_t)((((lane & 7) + ((lane >> 3) & 1) * 8) * RSTR) + ((lane >> 4) & 1) * 16);
    uint32_t boff  = (uint32_t)((((lane & 7) + ((lane >> 4) & 1) * 8) * RSTR) + ((lane >> 3) & 1) * 16);

    // cp.async mapping: 512 threads, 2 chunks each.
    // half 0 (tid 0-255): A^T chunk + B1 chunk. half 1: A2 chunk + B2 chunk.
    int half = tid >> 8;
    int t8   = tid & 255;
    int ar = t8 >> 4, ac = t8 & 15;      // A^T: 16 rows x 16 chunks
    int lr = t8 >> 1, lc = t8 & 1;       // token tiles: 128 rows x 2 chunks
    uint32_t aso = (uint32_t)(ar * ARSTR + ac * 16);
    uint32_t bso = (uint32_t)(lr * RSTR + lc * 16);
    int lc8 = lc * 8;

    float accR[2][4][4], accG[2][4][4];
#pragma unroll
    for (int mi = 0; mi < 2; mi++)
#pragma unroll
        for (int ni = 0; ni < 4; ni++)
#pragma unroll
            for (int r = 0; r < 4; r++) { accR[mi][ni][r] = 0.f; accG[mi][ni][r] = 0.f; }

    auto load_stage = [&](int st, int kt) {
        int k0 = kt * 16;
        uint32_t base = sb + (uint32_t)st * LSTAGE_B;
        if (half == 0) {
            cp16s(base + aso, AT + (size_t)(bz * D_ + k0 + ar) * S_ + sm0 + ac * 8);
            cp16s(base + ATILE_B + TILE_B + bso, B1 + (size_t)(n0 + lr) * K + k0 + lc8);
        } else {
            cp16s(base + ATILE_B + bso,          A2 + (size_t)(m0 + lr) * K + k0 + lc8);
            cp16s(base + ATILE_B + 2 * TILE_B + bso, B2 + (size_t)(n0 + lr) * K + k0 + lc8);
        }
    };

    int KT = K >> 4;
    load_stage(0, 0); cp_commit();
    load_stage(1, 1); cp_commit();

    for (int kt = 0; kt < KT; kt++) {
        if (kt == KT - 1) cp_wait<0>(); else cp_wait<1>();
        __syncthreads();
        if (kt + 2 < KT) { load_stage((kt + 2) % 3, kt + 2); cp_commit(); }

        uint32_t base = sb + (uint32_t)(kt % 3) * LSTAGE_B;
        uint32_t tA  = base;
        uint32_t tC  = base + ATILE_B;
        uint32_t tB1 = tC + TILE_B;
        uint32_t tB2 = tB1 + TILE_B;

        uint32_t af[8], bf[8];

        // --- refine: A from trans tile, B = Wr ---
        LDSM4(bf[0], bf[1], bf[2], bf[3], tB1 + (uint32_t)(wn * RSTR) + boff);
        LDSM4(bf[4], bf[5], bf[6], bf[7], tB1 + (uint32_t)((wn + 16) * RSTR) + boff);
#pragma unroll
        for (int mi = 0; mi < 2; mi++)
            LDSM4T(af[mi*4], af[mi*4+1], af[mi*4+2], af[mi*4+3],
                   tA + aoffT + (uint32_t)((wm + mi * 16) * 2));
#pragma unroll
        for (int mi = 0; mi < 2; mi++)
#pragma unroll
            for (int ni = 0; ni < 4; ni++)
                mma_fp16(accR[mi][ni], &af[mi*4], &bf[ni*2]);

        // --- gate: A = cur16 token-major, B = Wg ---
        LDSM4(bf[0], bf[1], bf[2], bf[3], tB2 + (uint32_t)(wn * RSTR) + boff);
        LDSM4(bf[4], bf[5], bf[6], bf[7], tB2 + (uint32_t)((wn + 16) * RSTR) + boff);
#pragma unroll
        for (int mi = 0; mi < 2; mi++)
            LDSM4(af[mi*4], af[mi*4+1], af[mi*4+2], af[mi*4+3],
                  tC + (uint32_t)((wm + mi * 16) * RSTR) + aoff);
#pragma unroll
        for (int mi = 0; mi < 2; mi++)
#pragma unroll
            for (int ni = 0; ni < 4; ni++)
                mma_fp16(accG[mi][ni], &af[mi*4], &bf[ni*2]);
    }

    // Fused combine epilogue
#pragma unroll
    for (int mi = 0; mi < 2; mi++) {
        int r0 = m0 + wm + mi * 16 + g;
#pragma unroll
        for (int ni = 0; ni < 4; ni++) {
            int c0 = n0 + wn + ni * 8 + t * 2;
            float rb0 = rbias[c0], rb1 = rbias[c0 + 1];
            float gb0 = gbias[c0], gb1 = gbias[c0 + 1];
            size_t o0 = (size_t)r0 * N + c0;
            size_t o1 = (size_t)(r0 + 8) * N + c0;
            float* aR = accR[mi][ni];
            float* aG = accG[mi][ni];
            float zR[4]  = {aR[0] + rb0, aR[1] + rb1, aR[2] + rb0, aR[3] + rb1};
            float zG[4]  = {aG[0] + gb0, aG[1] + gb1, aG[2] + gb0, aG[3] + gb1};
            size_t offs[4] = {o0, o0 + 1, o1, o1 + 1};
#pragma unroll
            for (int j = 0; j < 4; j++) {
                float gt = 1.f / (1.f + expf(-zG[j]));
                float res = gt * zR[j] + (1.f - gt) * orig[offs[j]];
                Cout[offs[j]] = res;
                C16[offs[j]] = __float2half(res);
            }
        }
    }
}

// ---------------------------------------------------------------------------
// Output GEMM: single-product fp16, token-major A. C = A*B + bias (fp32).
// ---------------------------------------------------------------------------
#define OSTAGE_B (2 * TILE_B)          // 12288 B
#define OGEMM_SMEM (3 * OSTAGE_B)      // 36864 B

__global__ void __launch_bounds__(256, 2) gemm_out(
        const __half* __restrict__ A, const __half* __restrict__ Bm,
        const float* __restrict__ bias,
        float* __restrict__ C, int M, int N, int K)
{
    extern __shared__ char smem[];
    uint32_t sb = smem_u32(smem);

    int tid  = threadIdx.x;
    int lane = tid & 31;
    int warp = tid >> 5;
    int g = lane >> 2, t = lane & 3;
    int wm = (warp >> 2) * 64;
    int wn = (warp & 3) * 32;
    int m0 = blockIdx.x * 128, n0 = blockIdx.y * 128;

    uint32_t aoff = (uint32_t)((((lane & 7) + ((lane >> 3) & 1) * 8) * RSTR) + ((lane >> 4) & 1) * 16);
    uint32_t boff = (uint32_t)((((lane & 7) + ((lane >> 4) & 1) * 8) * RSTR) + ((lane >> 3) & 1) * 16);

    int lr = tid >> 1;
    int lc8 = (tid & 1) * 8;
    uint32_t so = (uint32_t)(lr * RSTR + (tid & 1) * 16);

    float acc[4][4][4];
#pragma unroll
    for (int mi = 0; mi < 4; mi++)
#pragma unroll
        for (int ni = 0; ni < 4; ni++)
#pragma unroll
            for (int r = 0; r < 4; r++) acc[mi][ni][r] = 0.f;

    auto load_stage = [&](int st, int kt) {
        int k0 = kt * 16;
        uint32_t base = sb + (uint32_t)st * OSTAGE_B;
        cp16s(base + so,          A  + (size_t)(m0 + lr) * K + k0 + lc8);
        cp16s(base + TILE_B + so, Bm + (size_t)(n0 + lr) * K + k0 + lc8);
    };

    int KT = K >> 4;
    load_stage(0, 0); cp_commit();
    load_stage(1, 1); cp_commit();

    for (int kt = 0; kt < KT; kt++) {
        if (kt == KT - 1) cp_wait<0>(); else cp_wait<1>();
        __syncthreads();
        if (kt + 2 < KT) { load_stage((kt + 2) % 3, kt + 2); cp_commit(); }

        uint32_t base = sb + (uint32_t)(kt % 3) * OSTAGE_B;
        uint32_t tA = base, tB = base + TILE_B;

        uint32_t af[16], bf[8];
        LDSM4(bf[0], bf[1], bf[2], bf[3], tB + (uint32_t)(wn * RSTR) + boff);
        LDSM4(bf[4], bf[5], bf[6], bf[7], tB + (uint32_t)((wn + 16) * RSTR) + boff);
#pragma unroll
        for (int mi = 0; mi < 4; mi++)
            LDSM4(af[mi*4], af[mi*4+1], af[mi*4+2], af[mi*4+3],
                  tA + (uint32_t)((wm + mi * 16) * RSTR) + aoff);
#pragma unroll
        for (int mi = 0; mi < 4; mi++)
#pragma unroll
            for (int ni = 0; ni < 4; ni++)
                mma_fp16(acc[mi][ni], &af[mi*4], &bf[ni*2]);
    }

#pragma unroll
    for (int mi = 0; mi < 4; mi++) {
        int r0 = m0 + wm + mi * 16 + g;
#pragma unroll
        for (int ni = 0; ni < 4; ni++) {
            int c0 = n0 + wn + ni * 8 + t * 2;
            float bv0 = bias[c0], bv1 = bias[c0 + 1];
            size_t o0 = (size_t)r0 * N + c0;
            size_t o1 = (size_t)(r0 + 8) * N + c0;
            float* a4 = acc[mi][ni];
            C[o0]     = a4[0] + bv0;
            C[o0 + 1] = a4[1] + bv1;
            C[o1]     = a4[2] + bv0;
            C[o1 + 1] = a4[3] + bv1;
        }
    }
}

// ---------------------------------------------------------------------------
// Embedding + sinusoidal PE (+ fp16 copy for layer-0 gate A)
// ---------------------------------------------------------------------------
__global__ void embed_kernel(const int* __restrict__ ids,
                             const float* __restrict__ emb,
                             float* __restrict__ x,
                             __half* __restrict__ x16) {
    int row = blockIdx.x;
    int s   = row & (S_ - 1);
    int tok = ids[row];
    int d0  = threadIdx.x * 4;
    float4 e = *(const float4*)(emb + (size_t)tok * D_ + d0);
    const float cln = -logf(10000.0f) / (float)D_;
    float pe[4];
#pragma unroll
    for (int j = 0; j < 4; j += 2) {
        float freq = expf(cln * (float)(d0 + j));
        float a = (float)s * freq;
        pe[j]   = sinf(a);
        pe[j+1] = cosf(a);
    }
    float o[4] = {e.x + pe[0], e.y + pe[1], e.z + pe[2], e.w + pe[3]};
    *(float4*)(x + (size_t)row * D_ + d0) = *(float4*)o;
    __half2 p0 = __floats2half2_rn(o[0], o[1]);
    __half2 p1 = __floats2half2_rn(o[2], o[3]);
    uint2 packed = {*(uint32_t*)&p0, *(uint32_t*)&p1};
    *(uint2*)(x16 + (size_t)row * D_ + d0) = packed;
}

// ---------------------------------------------------------------------------
// fp16 convert (layer weights)
// ---------------------------------------------------------------------------
__global__ void conv16_kernel(const float* __restrict__ w,
                              __half* __restrict__ o, int n4) {
    int i = blockIdx.x * 256 + threadIdx.x;
    if (i >= n4) return;
    float4 v = ((const float4*)w)[i];
    __half2 p0 = __floats2half2_rn(v.x, v.y);
    __half2 p1 = __floats2half2_rn(v.z, v.w);
    uint2 packed = {*(uint32_t*)&p0, *(uint32_t*)&p1};
    ((uint2*)o)[i] = packed;
}

// ---------------------------------------------------------------------------
// outW (D,V) -> [V][D] fp16
// ---------------------------------------------------------------------------
__global__ void wout_t16_kernel(const float* __restrict__ w,
                                __half* __restrict__ o16) {
    __shared__ float tile[32][33];
    int v0 = blockIdx.x * 32, d0 = blockIdx.y * 32;
    int tx = threadIdx.x, ty = threadIdx.y;
#pragma unroll
    for (int i = 0; i < 4; i++)
        tile[ty + i * 8][tx] = w[(size_t)(d0 + ty + i * 8) * V_ + v0 + tx];
    __syncthreads();
#pragma unroll
    for (int i = 0; i < 4; i++) {
        size_t o = (size_t)(v0 + ty + i * 8) * D_ + d0 + tx;
        o16[o] = __float2half(tile[tx][ty + i * 8]);
    }
}

// ---------------------------------------------------------------------------
// LayerNorm statistics
// ---------------------------------------------------------------------------
__global__ void ln_stats_kernel(const float* __restrict__ x, float2* __restrict__ stats) {
    int row = blockIdx.x;
    float4 v = ((const float4*)(x + (size_t)row * D_))[threadIdx.x];
    float s = v.x + v.y + v.z + v.w;
    float q = v.x*v.x + v.y*v.y + v.z*v.z + v.w*v.w;
#pragma unroll
    for (int o = 16; o; o >>= 1) {
        s += __shfl_xor_sync(0xffffffffu, s, o);
        q += __shfl_xor_sync(0xffffffffu, q, o);
    }
    __shared__ float ss[8], sq[8];
    int w = threadIdx.x >> 5;
    if ((threadIdx.x & 31) == 0) { ss[w] = s; sq[w] = q; }
    __syncthreads();
    if (threadIdx.x == 0) {
        float S = 0.f, Q = 0.f;
#pragma unroll
        for (int i = 0; i < 8; i++) { S += ss[i]; Q += sq[i]; }
        float mu  = S / (float)D_;
        float var = Q / (float)D_ - mu * mu;
        stats[row] = make_float2(mu, rsqrtf(var + 1e-5f));
    }
}

// ---------------------------------------------------------------------------
// Apply LN while transposing (B,S,D)->(B,D,S)
// ---------------------------------------------------------------------------
__global__ void ln_transpose_kernel(const float* __restrict__ x,
                                    const float2* __restrict__ stats,
                                    const float* __restrict__ g,
                                    const float* __restrict__ bta,
                                    float* __restrict__ hT) {
    __shared__ float tile[32][33];
    int b  = blockIdx.z;
    int s0 = blockIdx.x * 32, d0 = blockIdx.y * 32;
    int tx = threadIdx.x, ty = threadIdx.y;
    float gg = g[d0 + tx], bb = bta[d0 + tx];
#pragma unroll
    for (int i = 0; i < 4; i++) {
        int s = s0 + ty + i * 8;
        float2 st = stats[b * S_ + s];
        float v = x[((size_t)(b * S_ + s)) * D_ + d0 + tx];
        tile[ty + i * 8][tx] = (v - st.x) * st.y * gg + bb;
    }
    __syncthreads();
#pragma unroll
    for (int i = 0; i < 4; i++) {
        int d = d0 + ty + i * 8;
        hT[((size_t)(b * D_ + d)) * S_ + s0 + tx] = tile[tx][ty + i * 8];
    }
}

// ---------------------------------------------------------------------------
// Final LN apply -> fp16
// ---------------------------------------------------------------------------
__global__ void apply_ln_kernel(const float* __restrict__ x,
                                const float2* __restrict__ stats,
                                const float* __restrict__ g,
                                const float* __restrict__ b,
                                __half* __restrict__ o16) {
    int row = blockIdx.x;
    int d0 = threadIdx.x * 4;
    float2 st = stats[row];
    float4 v  = *(const float4*)(x + (size_t)row * D_ + d0);
    float4 gg = *(const float4*)(g + d0);
    float4 bb = *(const float4*)(b + d0);
    __half2 p0 = __floats2half2_rn((v.x - st.x) * st.y * gg.x + bb.x,
                                   (v.y - st.x) * st.y * gg.y + bb.y);
    __half2 p1 = __floats2half2_rn((v.z - st.x) * st.y * gg.z + bb.z,
                                   (v.w - st.x) * st.y * gg.w + bb.w);
    uint2 packed = {*(uint32_t*)&p0, *(uint32_t*)&p1};
    *(uint2*)(o16 + (size_t)row * D_ + d0) = packed;
}

// ---------------------------------------------------------------------------
// Depthwise conv chain per (b,d) channel -> fp16 (B,D,S) output.
// ---------------------------------------------------------------------------
__global__ void __launch_bounds__(256) conv_kernel(const float* __restrict__ hT,
                                                   const float* __restrict__ lw,
                                                   const float* __restrict__ fw,
                                                   const float* __restrict__ mw,
                                                   __half* __restrict__ yT16) {
    int bd = blockIdx.x;
    int d  = bd & (D_ - 1);
    __shared__ float bufA[S_ + 64];
    __shared__ float bufB[S_ + 64];
    __shared__ float w3[3], wA[64], wB[64];
    int tid = threadIdx.x;
    if (tid < 64) {
        wA[tid] = fw[(size_t)d * 64 + tid];
        wB[tid] = fw[(size_t)(D_ + d) * 64 + tid];
    }
    if (tid < 3) w3[tid] = lw[d * 3 + tid];
    if (tid < 32) {
        bufA[tid] = 0.f; bufA[S_ + 32 + tid] = 0.f;
        bufB[tid] = 0.f; bufB[S_ + 32 + tid] = 0.f;
    }
    const float* cin = hT + (size_t)bd * S_;
    for (int i = tid; i < S_ / 4; i += 256)
        ((float4*)(bufA + 32))[i] = ((const float4*)cin)[i];
    __syncthreads();
    for (int s = tid; s < S_; s += 256)
        bufB[32 + s] = bufA[31 + s] * w3[0] + bufA[32 + s] * w3[1] + bufA[33 + s] * w3[2];
    __syncthreads();

    int s0 = tid * 8;
    float acc[8], win[8], nxt[8];

#pragma unroll
    for (int j = 0; j < 8; j++) { acc[j] = bufA[32 + s0 + j]; win[j] = bufB[s0 + j]; }
#pragma unroll
    for (int k0 = 0; k0 < 64; k0 += 8) {
#pragma unroll
        for (int j = 0; j < 8; j++) nxt[j] = bufB[s0 + 8 + k0 + j];
#pragma unroll
        for (int kk = 0; kk < 8; kk++) {
            float wk = wA[k0 + kk];
#pragma unroll
            for (int j = 0; j < 8; j++) {
                int ix = j + kk;
                acc[j] += (ix < 8 ? win[ix] : nxt[ix - 8]) * wk;
            }
        }
#pragma unroll
        for (int j = 0; j < 8; j++) win[j] = nxt[j];
    }
    __syncthreads();
#pragma unroll
    for (int j = 0; j < 8; j++) bufA[32 + s0 + j] = acc[j];
    __syncthreads();

    float mwd = mw[d];
#pragma unroll
    for (int j = 0; j < 8; j++) { acc[j] = 0.f; win[j] = bufA[s0 + j]; }
#pragma unroll
    for (int k0 = 0; k0 < 64; k0 += 8) {
#pragma unroll
        for (int j = 0; j < 8; j++) nxt[j] = bufA[s0 + 8 + k0 + j];
#pragma unroll
        for (int kk = 0; kk < 8; kk++) {
            float wk = wB[k0 + kk];
#pragma unroll
            for (int j = 0; j < 8; j++) {
                int ix = j + kk;
                acc[j] += (ix < 8 ? win[ix] : nxt[ix - 8]) * wk;
            }
        }
#pragma unroll
        for (int j = 0; j < 8; j++) win[j] = nxt[j];
    }
    __half hv[8];
#pragma unroll
    for (int j = 0; j < 8; j++) {
        float m = acc[j] * mwd;
        hv[j] = __float2half(m / (1.0f + expf(-m)));
    }
    *(uint4*)(yT16 + (size_t)bd * S_ + s0) = *(uint4*)hv;
}

// ---------------------------------------------------------------------------
// Host orchestration
// ---------------------------------------------------------------------------
static void* sym_addr(const void* sym) {
    void* p = nullptr;
    cudaGetSymbolAddress(&p, sym);
    return p;
}

extern "C" void kernel_launch(void* const* d_in, const int* in_sizes, int n_in,
                              void* d_out, int out_size) {
    (void)in_sizes; (void)n_in; (void)out_size;
    const int*   ids   = (const int*)d_in[0];
    const float* emb   = (const float*)d_in[1];
    const float* lw    = (const float*)d_in[2];
    const float* fw    = (const float*)d_in[3];
    const float* mw    = (const float*)d_in[4];
    const float* ln1g  = (const float*)d_in[5];
    const float* ln1b  = (const float*)d_in[6];
    const float* refW  = (const float*)d_in[7];
    const float* refb  = (const float*)d_in[8];
    const float* gateW = (const float*)d_in[9];
    const float* gateb = (const float*)d_in[10];
    const float* lnfg  = (const float*)d_in[11];
    const float* lnfb  = (const float*)d_in[12];
    const float* outW  = (const float*)d_in[13];
    const float* outb  = (const float*)d_in[14];
    float* out = (float*)d_out;

    float*  x0  = (float*)sym_addr(g_x0);
    float*  x1  = (float*)sym_addr(g_x1);
    float*  hT  = (float*)sym_addr(g_hT);
    float2* st  = (float2*)sym_addr(g_stats);
    __half* x016 = (__half*)sym_addr(g_x016);
    __half* x116 = (__half*)sym_addr(g_x116);
    __half* yT16 = (__half*)sym_addr(g_yT16);
    __half* wr16 = (__half*)sym_addr(g_wr16);
    __half* wg16 = (__half*)sym_addr(g_wg16);
    __half* xf16 = (__half*)sym_addr(g_xf16);
    __half* wo16 = (__half*)sym_addr(g_wo16);

    cudaFuncSetAttribute(gemm_layer, cudaFuncAttributeMaxDynamicSharedMemorySize, LGEMM_SMEM);
    cudaFuncSetAttribute(gemm_out,   cudaFuncAttributeMaxDynamicSharedMemorySize, OGEMM_SMEM);

    {
        int n4 = NL_ * D_ * D_ / 4;
        conv16_kernel<<<(n4 + 255) / 256, 256>>>(refW,  wr16, n4);
        conv16_kernel<<<(n4 + 255) / 256, 256>>>(gateW, wg16, n4);
        wout_t16_kernel<<<dim3(V_ / 32, D_ / 32), dim3(32, 8)>>>(outW, wo16);
    }

    embed_kernel<<<M_, 256>>>(ids, emb, x0, x016);

    float* cur = x0;        float* nxt = x1;
    __half *cur16 = x016, *nxt16 = x116;
    for (int l = 0; l < NL_; l++) {
        ln_stats_kernel<<<M_, 256>>>(cur, st);
        ln_transpose_kernel<<<dim3(S_/32, D_/32, B_), dim3(32, 8)>>>(
            cur, st, ln1g + (size_t)l * D_, ln1b + (size_t)l * D_, hT);
        conv_kernel<<<B_*D_, 256>>>(
            hT, lw + (size_t)l * D_ * 3, fw + (size_t)l * 2 * D_ * 64,
            mw + (size_t)l * D_, yT16);
        gemm_layer<<<dim3(M_/128, D_/128), 512, LGEMM_SMEM>>>(
            yT16, cur16,
            wr16 + (size_t)l * D_ * D_, wg16 + (size_t)l * D_ * D_,
            refb + (size_t)l * D_, gateb + (size_t)l * D_,
            cur, nxt, nxt16, D_, D_);
        { float* tf = cur; cur = nxt; nxt = tf; }
        { __half* th = cur16; cur16 = nxt16; nxt16 = th; }
    }

    ln_stats_kernel<<<M_, 256>>>(cur, st);
    apply_ln_kernel<<<M_, 256>>>(cur, st, lnfg, lnfb, xf16);
    gemm_out<<<dim3(M_/128, V_/128), 256, OGEMM_SMEM>>>(
        xf16, wo16, outb, out, M_, V_, D_);
}

// round 14
// speedup vs baseline: 1.0717x; 1.0479x over previous
#include <cuda_runtime.h>
#include <cuda_fp16.h>
#include <math.h>
#include <stdint.h>

#define B_  2
#define S_  2048
#define D_  1024
#define V_  32000
#define NL_ 6
#define M_  (B_*S_)   // 4096 tokens

// ---------------------------------------------------------------------------
// Scratch
// ---------------------------------------------------------------------------
__device__ float  g_x0[M_*D_];
__device__ float  g_x1[M_*D_];
__device__ float  g_hT[M_*D_];
__device__ float  g_ref[M_*D_];
__device__ float2 g_part[M_*32];                       // per-row LN partials (32/row)

__device__ __half g_x016[M_*D_], g_x116[M_*D_];
__device__ __half g_yT16[M_*D_];                       // conv out, (B,D,S) fp16
__device__ __half g_wr16[NL_*D_*D_];
__device__ __half g_wg16[NL_*D_*D_];
__device__ __half g_xf16[M_*D_];
__device__ __half g_wo16[(size_t)V_*D_];

// ---------------------------------------------------------------------------
// PTX helpers
// ---------------------------------------------------------------------------
__device__ __forceinline__ uint32_t smem_u32(const void* p) {
    uint32_t a;
    asm("{ .reg .u64 t; cvta.to.shared.u64 t, %1; cvt.u32.u64 %0, t; }" : "=r"(a) : "l"(p));
    return a;
}
__device__ __forceinline__ void cp16s(uint32_t saddr, const void* g) {
    asm volatile("cp.async.cg.shared.global [%0], [%1], 16;\n" :: "r"(saddr), "l"(g));
}
__device__ __forceinline__ void cp_commit() {
    asm volatile("cp.async.commit_group;\n" ::: "memory");
}
template<int N_> __device__ __forceinline__ void cp_wait() {
    asm volatile("cp.async.wait_group %0;\n" :: "n"(N_) : "memory");
}
__device__ __forceinline__ void mma_fp16(float* c, const uint32_t* a, const uint32_t* b) {
    asm volatile(
        "mma.sync.aligned.m16n8k16.row.col.f32.f16.f16.f32 "
        "{%0,%1,%2,%3}, {%4,%5,%6,%7}, {%8,%9}, {%0,%1,%2,%3};"
        : "+f"(c[0]), "+f"(c[1]), "+f"(c[2]), "+f"(c[3])
        : "r"(a[0]), "r"(a[1]), "r"(a[2]), "r"(a[3]), "r"(b[0]), "r"(b[1]));
}
#define LDSM4(r0, r1, r2, r3, addr) \
    asm volatile("ldmatrix.sync.aligned.m8n8.x4.shared.b16 {%0,%1,%2,%3}, [%4];" \
        : "=r"(r0), "=r"(r1), "=r"(r2), "=r"(r3) : "r"(addr))
#define LDSM4T(r0, r1, r2, r3, addr) \
    asm volatile("ldmatrix.sync.aligned.m8n8.x4.trans.shared.b16 {%0,%1,%2,%3}, [%4];" \
        : "=r"(r0), "=r"(r1), "=r"(r2), "=r"(r3) : "r"(addr))

#define RSTR   48                    // bytes per smem row (token-major tiles)
#define TILE_B (128 * RSTR)          // 6144 B per 128x16 fp16 tile

// ---------------------------------------------------------------------------
// Refine GEMM: A = yT16 (B,D,S) channel-major fp16 (ldmatrix.trans),
// B single fp16:  C = A*B + bias  (fp32 accum).
// CTA 128x128, BK=16, 8 warps (64x32), 3-stage cp.async pipeline.
// ---------------------------------------------------------------------------
#define ARSTR   272
#define ATILE_B (16 * ARSTR)                 // 4352 B
#define RSTAGE_B (ATILE_B + TILE_B)          // 10496 B
#define RGEMM_SMEM (3 * RSTAGE_B)            // 31488 B

__global__ void __launch_bounds__(256, 2) gemm_ref(
        const __half* __restrict__ AT,       // (B,D,S) fp16
        const __half* __restrict__ Bm,
        const float* __restrict__ bias,
        float* __restrict__ C, int N, int K)
{
    extern __shared__ char smem[];
    uint32_t sb = smem_u32(smem);

    int tid  = threadIdx.x;
    int lane = tid & 31;
    int warp = tid >> 5;
    int g = lane >> 2, t = lane & 3;
    int wm = (warp >> 2) * 64;
    int wn = (warp & 3) * 32;
    int m0 = blockIdx.x * 128, n0 = blockIdx.y * 128;
    int bz = m0 / S_;
    int sm0 = m0 & (S_ - 1);

    uint32_t aoffT = (uint32_t)((((lane & 7) + ((lane >> 4) & 1) * 8) * ARSTR) + ((lane >> 3) & 1) * 16);
    uint32_t boff = (uint32_t)((((lane & 7) + ((lane >> 4) & 1) * 8) * RSTR) + ((lane >> 3) & 1) * 16);

    int ar = tid >> 4, ac = tid & 15;
    int lr = tid >> 1;
    uint32_t aso = (uint32_t)(ar * ARSTR + ac * 16);
    uint32_t bso = (uint32_t)(lr * RSTR + (tid & 1) * 16);
    int lc8 = (tid & 1) * 8;

    float acc[4][4][4];
#pragma unroll
    for (int mi = 0; mi < 4; mi++)
#pragma unroll
        for (int ni = 0; ni < 4; ni++)
#pragma unroll
            for (int r = 0; r < 4; r++) acc[mi][ni][r] = 0.f;

    auto load_stage = [&](int st, int kt) {
        int k0 = kt * 16;
        uint32_t base = sb + (uint32_t)st * RSTAGE_B;
        cp16s(base + aso, AT + (size_t)(bz * D_ + k0 + ar) * S_ + sm0 + ac * 8);
        cp16s(base + ATILE_B + bso, Bm + (size_t)(n0 + lr) * K + k0 + lc8);
    };

    int KT = K >> 4;
    load_stage(0, 0); cp_commit();
    load_stage(1, 1); cp_commit();

    for (int kt = 0; kt < KT; kt++) {
        if (kt == KT - 1) cp_wait<0>(); else cp_wait<1>();
        __syncthreads();
        if (kt + 2 < KT) { load_stage((kt + 2) % 3, kt + 2); cp_commit(); }

        uint32_t base = sb + (uint32_t)(kt % 3) * RSTAGE_B;
        uint32_t tA = base, tB = base + ATILE_B;

        uint32_t af[16], bf[8];
        LDSM4(bf[0], bf[1], bf[2], bf[3], tB + (uint32_t)(wn * RSTR) + boff);
        LDSM4(bf[4], bf[5], bf[6], bf[7], tB + (uint32_t)((wn + 16) * RSTR) + boff);
#pragma unroll
        for (int mi = 0; mi < 4; mi++)
            LDSM4T(af[mi*4], af[mi*4+1], af[mi*4+2], af[mi*4+3],
                   tA + aoffT + (uint32_t)((wm + mi * 16) * 2));
#pragma unroll
        for (int mi = 0; mi < 4; mi++)
#pragma unroll
            for (int ni = 0; ni < 4; ni++)
                mma_fp16(acc[mi][ni], &af[mi*4], &bf[ni*2]);
    }

#pragma unroll
    for (int mi = 0; mi < 4; mi++) {
        int r0 = m0 + wm + mi * 16 + g;
#pragma unroll
        for (int ni = 0; ni < 4; ni++) {
            int c0 = n0 + wn + ni * 8 + t * 2;
            float bv0 = bias[c0], bv1 = bias[c0 + 1];
            size_t o0 = (size_t)r0 * N + c0;
            size_t o1 = (size_t)(r0 + 8) * N + c0;
            float* a4 = acc[mi][ni];
            C[o0]     = a4[0] + bv0;
            C[o0 + 1] = a4[1] + bv1;
            C[o1]     = a4[2] + bv0;
            C[o1 + 1] = a4[3] + bv1;
        }
    }
}

// ---------------------------------------------------------------------------
// Single-product fp16 GEMM (gate + output projection), token-major A.
// EPI 0 (output): C = acc + bias (fp32)
// EPI 1 (gate)  : s=sigmoid(acc+bias); x' = s*refined+(1-s)*orig -> fp32+fp16
//                 + per-row (sum,sumsq) LN partials: slot = blockIdx.y*4+(warp&3)
// ---------------------------------------------------------------------------
#define OSTAGE_B (2 * TILE_B)          // 12288 B
#define OGEMM_SMEM (3 * OSTAGE_B)      // 36864 B

template<int EPI>
__global__ void __launch_bounds__(256, 2) gemm_1p(
        const __half* __restrict__ A, const __half* __restrict__ Bm,
        const float* __restrict__ bias,
        const float* __restrict__ refined, const float* __restrict__ orig,
        float* __restrict__ C, __half* __restrict__ C16,
        float2* __restrict__ part,
        int M, int N, int K)
{
    extern __shared__ char smem[];
    uint32_t sb = smem_u32(smem);

    int tid  = threadIdx.x;
    int lane = tid & 31;
    int warp = tid >> 5;
    int g = lane >> 2, t = lane & 3;
    int wm = (warp >> 2) * 64;
    int wn = (warp & 3) * 32;
    int m0 = blockIdx.x * 128, n0 = blockIdx.y * 128;

    uint32_t aoff = (uint32_t)((((lane & 7) + ((lane >> 3) & 1) * 8) * RSTR) + ((lane >> 4) & 1) * 16);
    uint32_t boff = (uint32_t)((((lane & 7) + ((lane >> 4) & 1) * 8) * RSTR) + ((lane >> 3) & 1) * 16);

    int lr = tid >> 1;
    int lc8 = (tid & 1) * 8;
    uint32_t so = (uint32_t)(lr * RSTR + (tid & 1) * 16);

    float acc[4][4][4];
#pragma unroll
    for (int mi = 0; mi < 4; mi++)
#pragma unroll
        for (int ni = 0; ni < 4; ni++)
#pragma unroll
            for (int r = 0; r < 4; r++) acc[mi][ni][r] = 0.f;

    auto load_stage = [&](int st, int kt) {
        int k0 = kt * 16;
        uint32_t base = sb + (uint32_t)st * OSTAGE_B;
        cp16s(base + so,          A  + (size_t)(m0 + lr) * K + k0 + lc8);
        cp16s(base + TILE_B + so, Bm + (size_t)(n0 + lr) * K + k0 + lc8);
    };

    int KT = K >> 4;
    load_stage(0, 0); cp_commit();
    load_stage(1, 1); cp_commit();

    for (int kt = 0; kt < KT; kt++) {
        if (kt == KT - 1) cp_wait<0>(); else cp_wait<1>();
        __syncthreads();
        if (kt + 2 < KT) { load_stage((kt + 2) % 3, kt + 2); cp_commit(); }

        uint32_t base = sb + (uint32_t)(kt % 3) * OSTAGE_B;
        uint32_t tA = base, tB = base + TILE_B;

        uint32_t af[16], bf[8];
        LDSM4(bf[0], bf[1], bf[2], bf[3], tB + (uint32_t)(wn * RSTR) + boff);
        LDSM4(bf[4], bf[5], bf[6], bf[7], tB + (uint32_t)((wn + 16) * RSTR) + boff);
#pragma unroll
        for (int mi = 0; mi < 4; mi++)
            LDSM4(af[mi*4], af[mi*4+1], af[mi*4+2], af[mi*4+3],
                  tA + (uint32_t)((wm + mi * 16) * RSTR) + aoff);
#pragma unroll
        for (int mi = 0; mi < 4; mi++)
#pragma unroll
            for (int ni = 0; ni < 4; ni++)
                mma_fp16(acc[mi][ni], &af[mi*4], &bf[ni*2]);
    }

#pragma unroll
    for (int mi = 0; mi < 4; mi++) {
        int r0 = m0 + wm + mi * 16 + g;
        float sA = 0.f, qA = 0.f, sB = 0.f, qB = 0.f;
#pragma unroll
        for (int ni = 0; ni < 4; ni++) {
            int c0 = n0 + wn + ni * 8 + t * 2;
            float bv0 = bias[c0], bv1 = bias[c0 + 1];
            size_t o0 = (size_t)r0 * N + c0;
            size_t o1 = (size_t)(r0 + 8) * N + c0;
            float* a4 = acc[mi][ni];
            if (EPI == 0) {
                C[o0]     = a4[0] + bv0;
                C[o0 + 1] = a4[1] + bv1;
                C[o1]     = a4[2] + bv0;
                C[o1 + 1] = a4[3] + bv1;
            } else {
                float pre[4] = {a4[0] + bv0, a4[1] + bv1, a4[2] + bv0, a4[3] + bv1};
                size_t offs[4] = {o0, o0 + 1, o1, o1 + 1};
                float res[4];
#pragma unroll
                for (int j = 0; j < 4; j++) {
                    float gt = 1.f / (1.f + expf(-pre[j]));
                    res[j] = gt * refined[offs[j]] + (1.f - gt) * orig[offs[j]];
                    C[offs[j]] = res[j];
                    C16[offs[j]] = __float2half(res[j]);
                }
                sA += res[0] + res[1];
                qA += res[0]*res[0] + res[1]*res[1];
                sB += res[2] + res[3];
                qB += res[2]*res[2] + res[3]*res[3];
            }
        }
        if (EPI == 1) {
            // reduce across the 4 t-lanes (lane bits 0-1) -> per-warp 32-col sums
#pragma unroll
            for (int o = 1; o <= 2; o <<= 1) {
                sA += __shfl_xor_sync(0xffffffffu, sA, o);
                qA += __shfl_xor_sync(0xffffffffu, qA, o);
                sB += __shfl_xor_sync(0xffffffffu, sB, o);
                qB += __shfl_xor_sync(0xffffffffu, qB, o);
            }
            if (t == 0) {
                int slot = blockIdx.y * 4 + (warp & 3);   // unique per column-warp
                part[(size_t)r0 * 32 + slot]       = make_float2(sA, qA);
                part[(size_t)(r0 + 8) * 32 + slot] = make_float2(sB, qB);
            }
        }
    }
}

// ---------------------------------------------------------------------------
// Embedding + sinusoidal PE (+ fp16 copy + LN partials for layer 0)
// ---------------------------------------------------------------------------
__global__ void embed_kernel(const int* __restrict__ ids,
                             const float* __restrict__ emb,
                             float* __restrict__ x,
                             __half* __restrict__ x16,
                             float2* __restrict__ part) {
    int row = blockIdx.x;
    int s   = row & (S_ - 1);
    int tok = ids[row];
    int d0  = threadIdx.x * 4;
    float4 e = *(const float4*)(emb + (size_t)tok * D_ + d0);
    const float cln = -logf(10000.0f) / (float)D_;
    float pe[4];
#pragma unroll
    for (int j = 0; j < 4; j += 2) {
        float freq = expf(cln * (float)(d0 + j));
        float a = (float)s * freq;
        pe[j]   = sinf(a);
        pe[j+1] = cosf(a);
    }
    float o[4] = {e.x + pe[0], e.y + pe[1], e.z + pe[2], e.w + pe[3]};
    *(float4*)(x + (size_t)row * D_ + d0) = *(float4*)o;
    __half2 p0 = __floats2half2_rn(o[0], o[1]);
    __half2 p1 = __floats2half2_rn(o[2], o[3]);
    uint2 packed = {*(uint32_t*)&p0, *(uint32_t*)&p1};
    *(uint2*)(x16 + (size_t)row * D_ + d0) = packed;

    // LN partials: block covers the whole row -> write slot 0, zero 1..31
    float sv = o[0] + o[1] + o[2] + o[3];
    float qv = o[0]*o[0] + o[1]*o[1] + o[2]*o[2] + o[3]*o[3];
#pragma unroll
    for (int off = 16; off; off >>= 1) {
        sv += __shfl_xor_sync(0xffffffffu, sv, off);
        qv += __shfl_xor_sync(0xffffffffu, qv, off);
    }
    __shared__ float ss[8], sq[8];
    int w = threadIdx.x >> 5;
    if ((threadIdx.x & 31) == 0) { ss[w] = sv; sq[w] = qv; }
    __syncthreads();
    if (threadIdx.x == 0) {
        float S = 0.f, Q = 0.f;
#pragma unroll
        for (int i = 0; i < 8; i++) { S += ss[i]; Q += sq[i]; }
        part[(size_t)row * 32] = make_float2(S, Q);
    } else if (threadIdx.x < 32) {
        part[(size_t)row * 32 + threadIdx.x] = make_float2(0.f, 0.f);
    }
}

// ---------------------------------------------------------------------------
// fp16 convert (layer weights)
// ---------------------------------------------------------------------------
__global__ void conv16_kernel(const float* __restrict__ w,
                              __half* __restrict__ o, int n4) {
    int i = blockIdx.x * 256 + threadIdx.x;
    if (i >= n4) return;
    float4 v = ((const float4*)w)[i];
    __half2 p0 = __floats2half2_rn(v.x, v.y);
    __half2 p1 = __floats2half2_rn(v.z, v.w);
    uint2 packed = {*(uint32_t*)&p0, *(uint32_t*)&p1};
    ((uint2*)o)[i] = packed;
}

// ---------------------------------------------------------------------------
// outW (D,V) -> [V][D] fp16
// ---------------------------------------------------------------------------
__global__ void wout_t16_kernel(const float* __restrict__ w,
                                __half* __restrict__ o16) {
    __shared__ float tile[32][33];
    int v0 = blockIdx.x * 32, d0 = blockIdx.y * 32;
    int tx = threadIdx.x, ty = threadIdx.y;
#pragma unroll
    for (int i = 0; i < 4; i++)
        tile[ty + i * 8][tx] = w[(size_t)(d0 + ty + i * 8) * V_ + v0 + tx];
    __syncthreads();
#pragma unroll
    for (int i = 0; i < 4; i++) {
        size_t o = (size_t)(v0 + ty + i * 8) * D_ + d0 + tx;
        o16[o] = __float2half(tile[tx][ty + i * 8]);
    }
}

// ---------------------------------------------------------------------------
// Apply LN while transposing (B,S,D)->(B,D,S); stats from 32 partials/row.
// ---------------------------------------------------------------------------
__global__ void ln_transpose_kernel(const float* __restrict__ x,
                                    const float2* __restrict__ part,
                                    const float* __restrict__ g,
                                    const float* __restrict__ bta,
                                    float* __restrict__ hT) {
    __shared__ float tile[32][33];
    __shared__ float2 sstat[32];
    int b  = blockIdx.z;
    int s0 = blockIdx.x * 32, d0 = blockIdx.y * 32;
    int tx = threadIdx.x, ty = threadIdx.y;
    int tid = ty * 32 + tx;
    if (tid < 32) {
        size_t row = (size_t)(b * S_ + s0 + tid);
        float s = 0.f, q = 0.f;
#pragma unroll
        for (int i = 0; i < 32; i++) {
            float2 p = part[row * 32 + i];
            s += p.x; q += p.y;
        }
        float mu  = s / (float)D_;
        float var = q / (float)D_ - mu * mu;
        sstat[tid] = make_float2(mu, rsqrtf(var + 1e-5f));
    }
    __syncthreads();
    float gg = g[d0 + tx], bb = bta[d0 + tx];
#pragma unroll
    for (int i = 0; i < 4; i++) {
        int sl = ty + i * 8;
        float2 st = sstat[sl];
        float v = x[((size_t)(b * S_ + s0 + sl)) * D_ + d0 + tx];
        tile[sl][tx] = (v - st.x) * st.y * gg + bb;
    }
    __syncthreads();
#pragma unroll
    for (int i = 0; i < 4; i++) {
        int d = d0 + ty + i * 8;
        hT[((size_t)(b * D_ + d)) * S_ + s0 + tx] = tile[tx][ty + i * 8];
    }
}

// ---------------------------------------------------------------------------
// Final LN apply -> fp16; stats from 32 partials/row (broadcast reads).
// ---------------------------------------------------------------------------
__global__ void apply_ln_kernel(const float* __restrict__ x,
                                const float2* __restrict__ part,
                                const float* __restrict__ g,
                                const float* __restrict__ b,
                                __half* __restrict__ o16) {
    int row = blockIdx.x;
    float s = 0.f, q = 0.f;
#pragma unroll
    for (int i = 0; i < 32; i++) {
        float2 p = part[(size_t)row * 32 + i];
        s += p.x; q += p.y;
    }
    float mu  = s / (float)D_;
    float var = q / (float)D_ - mu * mu;
    float rstd = rsqrtf(var + 1e-5f);

    int d0 = threadIdx.x * 4;
    float4 v  = *(const float4*)(x + (size_t)row * D_ + d0);
    float4 gg = *(const float4*)(g + d0);
    float4 bb = *(const float4*)(b + d0);
    __half2 p0 = __floats2half2_rn((v.x - mu) * rstd * gg.x + bb.x,
                                   (v.y - mu) * rstd * gg.y + bb.y);
    __half2 p1 = __floats2half2_rn((v.z - mu) * rstd * gg.z + bb.z,
                                   (v.w - mu) * rstd * gg.w + bb.w);
    uint2 packed = {*(uint32_t*)&p0, *(uint32_t*)&p1};
    *(uint2*)(o16 + (size_t)row * D_ + d0) = packed;
}

// ---------------------------------------------------------------------------
// Depthwise conv chain per (b,d) channel -> fp16 (B,D,S) output.
// ---------------------------------------------------------------------------
__global__ void __launch_bounds__(256) conv_kernel(const float* __restrict__ hT,
                                                   const float* __restrict__ lw,
                                                   const float* __restrict__ fw,
                                                   const float* __restrict__ mw,
                                                   __half* __restrict__ yT16) {
    int bd = blockIdx.x;
    int d  = bd & (D_ - 1);
    __shared__ float bufA[S_ + 64];
    __shared__ float bufB[S_ + 64];
    __shared__ float w3[3], wA[64], wB[64];
    int tid = threadIdx.x;
    if (tid < 64) {
        wA[tid] = fw[(size_t)d * 64 + tid];
        wB[tid] = fw[(size_t)(D_ + d) * 64 + tid];
    }
    if (tid < 3) w3[tid] = lw[d * 3 + tid];
    if (tid < 32) {
        bufA[tid] = 0.f; bufA[S_ + 32 + tid] = 0.f;
        bufB[tid] = 0.f; bufB[S_ + 32 + tid] = 0.f;
    }
    const float* cin = hT + (size_t)bd * S_;
    for (int i = tid; i < S_ / 4; i += 256)
        ((float4*)(bufA + 32))[i] = ((const float4*)cin)[i];
    __syncthreads();
    for (int s = tid; s < S_; s += 256)
        bufB[32 + s] = bufA[31 + s] * w3[0] + bufA[32 + s] * w3[1] + bufA[33 + s] * w3[2];
    __syncthreads();

    int s0 = tid * 8;
    float acc[8], win[8], nxt[8];

#pragma unroll
    for (int j = 0; j < 8; j++) { acc[j] = bufA[32 + s0 + j]; win[j] = bufB[s0 + j]; }
#pragma unroll
    for (int k0 = 0; k0 < 64; k0 += 8) {
#pragma unroll
        for (int j = 0; j < 8; j++) nxt[j] = bufB[s0 + 8 + k0 + j];
#pragma unroll
        for (int kk = 0; kk < 8; kk++) {
            float wk = wA[k0 + kk];
#pragma unroll
            for (int j = 0; j < 8; j++) {
                int ix = j + kk;
                acc[j] += (ix < 8 ? win[ix] : nxt[ix - 8]) * wk;
            }
        }
#pragma unroll
        for (int j = 0; j < 8; j++) win[j] = nxt[j];
    }
    __syncthreads();
#pragma unroll
    for (int j = 0; j < 8; j++) bufA[32 + s0 + j] = acc[j];
    __syncthreads();

    float mwd = mw[d];
#pragma unroll
    for (int j = 0; j < 8; j++) { acc[j] = 0.f; win[j] = bufA[s0 + j]; }
#pragma unroll
    for (int k0 = 0; k0 < 64; k0 += 8) {
#pragma unroll
        for (int j = 0; j < 8; j++) nxt[j] = bufA[s0 + 8 + k0 + j];
#pragma unroll
        for (int kk = 0; kk < 8; kk++) {
            float wk = wB[k0 + kk];
#pragma unroll
            for (int j = 0; j < 8; j++) {
                int ix = j + kk;
                acc[j] += (ix < 8 ? win[ix] : nxt[ix - 8]) * wk;
            }
        }
#pragma unroll
        for (int j = 0; j < 8; j++) win[j] = nxt[j];
    }
    __half hv[8];
#pragma unroll
    for (int j = 0; j < 8; j++) {
        float m = acc[j] * mwd;
        hv[j] = __float2half(m / (1.0f + expf(-m)));
    }
    *(uint4*)(yT16 + (size_t)bd * S_ + s0) = *(uint4*)hv;
}

// ---------------------------------------------------------------------------
// Host orchestration
// ---------------------------------------------------------------------------
static void* sym_addr(const void* sym) {
    void* p = nullptr;
    cudaGetSymbolAddress(&p, sym);
    return p;
}

extern "C" void kernel_launch(void* const* d_in, const int* in_sizes, int n_in,
                              void* d_out, int out_size) {
    (void)in_sizes; (void)n_in; (void)out_size;
    const int*   ids   = (const int*)d_in[0];
    const float* emb   = (const float*)d_in[1];
    const float* lw    = (const float*)d_in[2];
    const float* fw    = (const float*)d_in[3];
    const float* mw    = (const float*)d_in[4];
    const float* ln1g  = (const float*)d_in[5];
    const float* ln1b  = (const float*)d_in[6];
    const float* refW  = (const float*)d_in[7];
    const float* refb  = (const float*)d_in[8];
    const float* gateW = (const float*)d_in[9];
    const float* gateb = (const float*)d_in[10];
    const float* lnfg  = (const float*)d_in[11];
    const float* lnfb  = (const float*)d_in[12];
    const float* outW  = (const float*)d_in[13];
    const float* outb  = (const float*)d_in[14];
    float* out = (float*)d_out;

    float*  x0  = (float*)sym_addr(g_x0);
    float*  x1  = (float*)sym_addr(g_x1);
    float*  hT  = (float*)sym_addr(g_hT);
    float*  rf  = (float*)sym_addr(g_ref);
    float2* pt  = (float2*)sym_addr(g_part);
    __half* x016 = (__half*)sym_addr(g_x016);
    __half* x116 = (__half*)sym_addr(g_x116);
    __half* yT16 = (__half*)sym_addr(g_yT16);
    __half* wr16 = (__half*)sym_addr(g_wr16);
    __half* wg16 = (__half*)sym_addr(g_wg16);
    __half* xf16 = (__half*)sym_addr(g_xf16);
    __half* wo16 = (__half*)sym_addr(g_wo16);

    cudaFuncSetAttribute(gemm_ref,    cudaFuncAttributeMaxDynamicSharedMemorySize, RGEMM_SMEM);
    cudaFuncSetAttribute(gemm_1p<0>,  cudaFuncAttributeMaxDynamicSharedMemorySize, OGEMM_SMEM);
    cudaFuncSetAttribute(gemm_1p<1>,  cudaFuncAttributeMaxDynamicSharedMemorySize, OGEMM_SMEM);

    {
        int n4 = NL_ * D_ * D_ / 4;
        conv16_kernel<<<(n4 + 255) / 256, 256>>>(refW,  wr16, n4);
        conv16_kernel<<<(n4 + 255) / 256, 256>>>(gateW, wg16, n4);
        wout_t16_kernel<<<dim3(V_ / 32, D_ / 32), dim3(32, 8)>>>(outW, wo16);
    }

    embed_kernel<<<M_, 256>>>(ids, emb, x0, x016, pt);

    float* cur = x0;        float* nxt = x1;
    __half *cur16 = x016, *nxt16 = x116;
    for (int l = 0; l < NL_; l++) {
        ln_transpose_kernel<<<dim3(S_/32, D_/32, B_), dim3(32, 8)>>>(
            cur, pt, ln1g + (size_t)l * D_, ln1b + (size_t)l * D_, hT);
        conv_kernel<<<B_*D_, 256>>>(
            hT, lw + (size_t)l * D_ * 3, fw + (size_t)l * 2 * D_ * 64,
            mw + (size_t)l * D_, yT16);
        gemm_ref<<<dim3(M_/128, D_/128), 256, RGEMM_SMEM>>>(
            yT16, wr16 + (size_t)l * D_ * D_,
            refb + (size_t)l * D_, rf, D_, D_);
        gemm_1p<1><<<dim3(M_/128, D_/128), 256, OGEMM_SMEM>>>(
            cur16, wg16 + (size_t)l * D_ * D_,
            gateb + (size_t)l * D_, rf, cur, nxt, nxt16, pt,
            M_, D_, D_);
        { float* tf = cur; cur = nxt; nxt = tf; }
        { __half* th = cur16; cur16 = nxt16; nxt16 = th; }
    }

    apply_ln_kernel<<<M_, 256>>>(cur, pt, lnfg, lnfb, xf16);
    gemm_1p<0><<<dim3(M_/128, V_/128), 256, OGEMM_SMEM>>>(
        xf16, wo16, outb, nullptr, nullptr, out, nullptr, nullptr, M_, V_, D_);
}

// round 15
// speedup vs baseline: 1.1415x; 1.0652x over previous
#include <cuda_runtime.h>
#include <cuda_fp16.h>
#include <math.h>
#include <stdint.h>

#define B_  2
#define S_  2048
#define D_  1024
#define V_  32000
#define NL_ 6
#define M_  (B_*S_)   // 4096 tokens

// ---------------------------------------------------------------------------
// Scratch
// ---------------------------------------------------------------------------
__device__ float  g_x0[M_*D_];
__device__ float  g_x1[M_*D_];
__device__ float  g_hT[M_*D_];
__device__ float  g_ref[M_*D_];
__device__ float2 g_stats[M_];

__device__ __half g_x016[M_*D_], g_x116[M_*D_];
__device__ __half g_yT16[M_*D_];                       // conv out, (B,D,S) fp16
__device__ __half g_wr16[NL_*D_*D_];
__device__ __half g_wg16[NL_*D_*D_];
__device__ __half g_xf16[M_*D_];
__device__ __half g_wo16[(size_t)V_*D_];

// ---------------------------------------------------------------------------
// PTX helpers
// ---------------------------------------------------------------------------
__device__ __forceinline__ uint32_t smem_u32(const void* p) {
    uint32_t a;
    asm("{ .reg .u64 t; cvta.to.shared.u64 t, %1; cvt.u32.u64 %0, t; }" : "=r"(a) : "l"(p));
    return a;
}
__device__ __forceinline__ void cp16s(uint32_t saddr, const void* g) {
    asm volatile("cp.async.cg.shared.global [%0], [%1], 16;\n" :: "r"(saddr), "l"(g));
}
__device__ __forceinline__ void cp_commit() {
    asm volatile("cp.async.commit_group;\n" ::: "memory");
}
template<int N_> __device__ __forceinline__ void cp_wait() {
    asm volatile("cp.async.wait_group %0;\n" :: "n"(N_) : "memory");
}
__device__ __forceinline__ void mma_fp16(float* c, const uint32_t* a, const uint32_t* b) {
    asm volatile(
        "mma.sync.aligned.m16n8k16.row.col.f32.f16.f16.f32 "
        "{%0,%1,%2,%3}, {%4,%5,%6,%7}, {%8,%9}, {%0,%1,%2,%3};"
        : "+f"(c[0]), "+f"(c[1]), "+f"(c[2]), "+f"(c[3])
        : "r"(a[0]), "r"(a[1]), "r"(a[2]), "r"(a[3]), "r"(b[0]), "r"(b[1]));
}
#define LDSM4(r0, r1, r2, r3, addr) \
    asm volatile("ldmatrix.sync.aligned.m8n8.x4.shared.b16 {%0,%1,%2,%3}, [%4];" \
        : "=r"(r0), "=r"(r1), "=r"(r2), "=r"(r3) : "r"(addr))
#define LDSM4T(r0, r1, r2, r3, addr) \
    asm volatile("ldmatrix.sync.aligned.m8n8.x4.trans.shared.b16 {%0,%1,%2,%3}, [%4];" \
        : "=r"(r0), "=r"(r1), "=r"(r2), "=r"(r3) : "r"(addr))

// BK = 32. Token-major tile rows hold 32 fp16 = 64B, padded to 80B
// (odd multiple of 16 -> conflict-free ldmatrix phases and cp.async stores).
#define RSTR2   80
#define TILE2_B (128 * RSTR2)        // 10240 B per 128x32 fp16 tile

// ---------------------------------------------------------------------------
// Refine GEMM: A = yT16 (B,D,S) channel-major fp16 (ldmatrix.trans),
// B single fp16:  C = A*B + bias  (fp32 accum).
// CTA 128x128, BK=32, 8 warps (64x32), 3-stage cp.async pipeline.
// A^T smem tile: 32 k-rows x 256B, stride 272B.
// ---------------------------------------------------------------------------
#define ARSTR    272
#define ATILE2_B (32 * ARSTR)                // 8704 B
#define RSTAGE_B (ATILE2_B + TILE2_B)        // 18944 B
#define RGEMM_SMEM (3 * RSTAGE_B)            // 56832 B

__global__ void __launch_bounds__(256, 2) gemm_ref(
        const __half* __restrict__ AT,       // (B,D,S) fp16
        const __half* __restrict__ Bm,
        const float* __restrict__ bias,
        float* __restrict__ C, int N, int K)
{
    extern __shared__ char smem[];
    uint32_t sb = smem_u32(smem);

    int tid  = threadIdx.x;
    int lane = tid & 31;
    int warp = tid >> 5;
    int g = lane >> 2, t = lane & 3;
    int wm = (warp >> 2) * 64;
    int wn = (warp & 3) * 32;
    int m0 = blockIdx.x * 128, n0 = blockIdx.y * 128;
    int bz = m0 / S_;
    int sm0 = m0 & (S_ - 1);

    uint32_t aoffT = (uint32_t)((((lane & 7) + ((lane >> 4) & 1) * 8) * ARSTR) + ((lane >> 3) & 1) * 16);
    uint32_t boff  = (uint32_t)((((lane & 7) + ((lane >> 4) & 1) * 8) * RSTR2) + ((lane >> 3) & 1) * 16);

    float acc[4][4][4];
#pragma unroll
    for (int mi = 0; mi < 4; mi++)
#pragma unroll
        for (int ni = 0; ni < 4; ni++)
#pragma unroll
            for (int r = 0; r < 4; r++) acc[mi][ni][r] = 0.f;

    auto load_stage = [&](int st, int kt) {
        int k0 = kt * 32;
        uint32_t base = sb + (uint32_t)st * RSTAGE_B;
#pragma unroll
        for (int i = 0; i < 2; i++) {
            int id = tid + i * 256;
            // A^T: 32 k-rows x 16 chunks of 16B
            int r = id >> 4, c = id & 15;
            cp16s(base + (uint32_t)(r * ARSTR + c * 16),
                  AT + (size_t)(bz * D_ + k0 + r) * S_ + sm0 + c * 8);
            // B: 128 rows x 4 chunks of 16B
            int br = id >> 2, bc = id & 3;
            cp16s(base + ATILE2_B + (uint32_t)(br * RSTR2 + bc * 16),
                  Bm + (size_t)(n0 + br) * K + k0 + bc * 8);
        }
    };

    int KT = K >> 5;
    load_stage(0, 0); cp_commit();
    load_stage(1, 1); cp_commit();

    for (int kt = 0; kt < KT; kt++) {
        if (kt == KT - 1) cp_wait<0>(); else cp_wait<1>();
        __syncthreads();
        if (kt + 2 < KT) { load_stage((kt + 2) % 3, kt + 2); cp_commit(); }

        uint32_t base = sb + (uint32_t)(kt % 3) * RSTAGE_B;
        uint32_t tA = base, tB = base + ATILE2_B;

#pragma unroll
        for (int ks = 0; ks < 2; ks++) {
            uint32_t af[16], bf[8];
            uint32_t bks = tB + (uint32_t)(ks * 32);
            LDSM4(bf[0], bf[1], bf[2], bf[3], bks + (uint32_t)(wn * RSTR2) + boff);
            LDSM4(bf[4], bf[5], bf[6], bf[7], bks + (uint32_t)((wn + 16) * RSTR2) + boff);
            uint32_t aks = tA + (uint32_t)(ks * 16 * ARSTR);
#pragma unroll
            for (int mi = 0; mi < 4; mi++)
                LDSM4T(af[mi*4], af[mi*4+1], af[mi*4+2], af[mi*4+3],
                       aks + aoffT + (uint32_t)((wm + mi * 16) * 2));
#pragma unroll
            for (int mi = 0; mi < 4; mi++)
#pragma unroll
                for (int ni = 0; ni < 4; ni++)
                    mma_fp16(acc[mi][ni], &af[mi*4], &bf[ni*2]);
        }
    }

#pragma unroll
    for (int mi = 0; mi < 4; mi++) {
        int r0 = m0 + wm + mi * 16 + g;
#pragma unroll
        for (int ni = 0; ni < 4; ni++) {
            int c0 = n0 + wn + ni * 8 + t * 2;
            float bv0 = bias[c0], bv1 = bias[c0 + 1];
            size_t o0 = (size_t)r0 * N + c0;
            size_t o1 = (size_t)(r0 + 8) * N + c0;
            float* a4 = acc[mi][ni];
            C[o0]     = a4[0] + bv0;
            C[o0 + 1] = a4[1] + bv1;
            C[o1]     = a4[2] + bv0;
            C[o1 + 1] = a4[3] + bv1;
        }
    }
}

// ---------------------------------------------------------------------------
// Single-product fp16 GEMM (gate + output projection), token-major A, BK=32.
// EPI 0 (output): C = acc + bias (fp32)
// EPI 1 (gate)  : s=sigmoid(acc+bias); x' = s*refined+(1-s)*orig -> fp32+fp16
// ---------------------------------------------------------------------------
#define OSTAGE_B (2 * TILE2_B)         // 20480 B
#define OGEMM_SMEM (3 * OSTAGE_B)      // 61440 B

template<int EPI>
__global__ void __launch_bounds__(256, 2) gemm_1p(
        const __half* __restrict__ A, const __half* __restrict__ Bm,
        const float* __restrict__ bias,
        const float* __restrict__ refined, const float* __restrict__ orig,
        float* __restrict__ C, __half* __restrict__ C16,
        int M, int N, int K)
{
    extern __shared__ char smem[];
    uint32_t sb = smem_u32(smem);

    int tid  = threadIdx.x;
    int lane = tid & 31;
    int warp = tid >> 5;
    int g = lane >> 2, t = lane & 3;
    int wm = (warp >> 2) * 64;
    int wn = (warp & 3) * 32;
    int m0 = blockIdx.x * 128, n0 = blockIdx.y * 128;

    uint32_t aoff = (uint32_t)((((lane & 7) + ((lane >> 3) & 1) * 8) * RSTR2) + ((lane >> 4) & 1) * 16);
    uint32_t boff = (uint32_t)((((lane & 7) + ((lane >> 4) & 1) * 8) * RSTR2) + ((lane >> 3) & 1) * 16);

    float acc[4][4][4];
#pragma unroll
    for (int mi = 0; mi < 4; mi++)
#pragma unroll
        for (int ni = 0; ni < 4; ni++)
#pragma unroll
            for (int r = 0; r < 4; r++) acc[mi][ni][r] = 0.f;

    auto load_stage = [&](int st, int kt) {
        int k0 = kt * 32;
        uint32_t base = sb + (uint32_t)st * OSTAGE_B;
#pragma unroll
        for (int i = 0; i < 2; i++) {
            int id = tid + i * 256;
            int r = id >> 2, c = id & 3;
            uint32_t so = (uint32_t)(r * RSTR2 + c * 16);
            cp16s(base + so,           A  + (size_t)(m0 + r) * K + k0 + c * 8);
            cp16s(base + TILE2_B + so, Bm + (size_t)(n0 + r) * K + k0 + c * 8);
        }
    };

    int KT = K >> 5;
    load_stage(0, 0); cp_commit();
    load_stage(1, 1); cp_commit();

    for (int kt = 0; kt < KT; kt++) {
        if (kt == KT - 1) cp_wait<0>(); else cp_wait<1>();
        __syncthreads();
        if (kt + 2 < KT) { load_stage((kt + 2) % 3, kt + 2); cp_commit(); }

        uint32_t base = sb + (uint32_t)(kt % 3) * OSTAGE_B;
        uint32_t tA = base, tB = base + TILE2_B;

#pragma unroll
        for (int ks = 0; ks < 2; ks++) {
            uint32_t af[16], bf[8];
            uint32_t bks = tB + (uint32_t)(ks * 32);
            uint32_t aks = tA + (uint32_t)(ks * 32);
            LDSM4(bf[0], bf[1], bf[2], bf[3], bks + (uint32_t)(wn * RSTR2) + boff);
            LDSM4(bf[4], bf[5], bf[6], bf[7], bks + (uint32_t)((wn + 16) * RSTR2) + boff);
#pragma unroll
            for (int mi = 0; mi < 4; mi++)
                LDSM4(af[mi*4], af[mi*4+1], af[mi*4+2], af[mi*4+3],
                      aks + (uint32_t)((wm + mi * 16) * RSTR2) + aoff);
#pragma unroll
            for (int mi = 0; mi < 4; mi++)
#pragma unroll
                for (int ni = 0; ni < 4; ni++)
                    mma_fp16(acc[mi][ni], &af[mi*4], &bf[ni*2]);
        }
    }

#pragma unroll
    for (int mi = 0; mi < 4; mi++) {
        int r0 = m0 + wm + mi * 16 + g;
#pragma unroll
        for (int ni = 0; ni < 4; ni++) {
            int c0 = n0 + wn + ni * 8 + t * 2;
            float bv0 = bias[c0], bv1 = bias[c0 + 1];
            size_t o0 = (size_t)r0 * N + c0;
            size_t o1 = (size_t)(r0 + 8) * N + c0;
            float* a4 = acc[mi][ni];
            if (EPI == 0) {
                C[o0]     = a4[0] + bv0;
                C[o0 + 1] = a4[1] + bv1;
                C[o1]     = a4[2] + bv0;
                C[o1 + 1] = a4[3] + bv1;
            } else {
                float pre[4] = {a4[0] + bv0, a4[1] + bv1, a4[2] + bv0, a4[3] + bv1};
                size_t offs[4] = {o0, o0 + 1, o1, o1 + 1};
#pragma unroll
                for (int j = 0; j < 4; j++) {
                    float gt = 1.f / (1.f + expf(-pre[j]));
                    float res = gt * refined[offs[j]] + (1.f - gt) * orig[offs[j]];
                    C[offs[j]] = res;
                    C16[offs[j]] = __float2half(res);
                }
            }
        }
    }
}

// ---------------------------------------------------------------------------
// Embedding + sinusoidal PE (+ fp16 copy for layer-0 gate A)
// ---------------------------------------------------------------------------
__global__ void embed_kernel(const int* __restrict__ ids,
                             const float* __restrict__ emb,
                             float* __restrict__ x,
                             __half* __restrict__ x16) {
    int row = blockIdx.x;
    int s   = row & (S_ - 1);
    int tok = ids[row];
    int d0  = threadIdx.x * 4;
    float4 e = *(const float4*)(emb + (size_t)tok * D_ + d0);
    const float cln = -logf(10000.0f) / (float)D_;
    float pe[4];
#pragma unroll
    for (int j = 0; j < 4; j += 2) {
        float freq = expf(cln * (float)(d0 + j));
        float a = (float)s * freq;
        pe[j]   = sinf(a);
        pe[j+1] = cosf(a);
    }
    float o[4] = {e.x + pe[0], e.y + pe[1], e.z + pe[2], e.w + pe[3]};
    *(float4*)(x + (size_t)row * D_ + d0) = *(float4*)o;
    __half2 p0 = __floats2half2_rn(o[0], o[1]);
    __half2 p1 = __floats2half2_rn(o[2], o[3]);
    uint2 packed = {*(uint32_t*)&p0, *(uint32_t*)&p1};
    *(uint2*)(x16 + (size_t)row * D_ + d0) = packed;
}

// ---------------------------------------------------------------------------
// fp16 convert (layer weights)
// ---------------------------------------------------------------------------
__global__ void conv16_kernel(const float* __restrict__ w,
                              __half* __restrict__ o, int n4) {
    int i = blockIdx.x * 256 + threadIdx.x;
    if (i >= n4) return;
    float4 v = ((const float4*)w)[i];
    __half2 p0 = __floats2half2_rn(v.x, v.y);
    __half2 p1 = __floats2half2_rn(v.z, v.w);
    uint2 packed = {*(uint32_t*)&p0, *(uint32_t*)&p1};
    ((uint2*)o)[i] = packed;
}

// ---------------------------------------------------------------------------
// outW (D,V) -> [V][D] fp16
// ---------------------------------------------------------------------------
__global__ void wout_t16_kernel(const float* __restrict__ w,
                                __half* __restrict__ o16) {
    __shared__ float tile[32][33];
    int v0 = blockIdx.x * 32, d0 = blockIdx.y * 32;
    int tx = threadIdx.x, ty = threadIdx.y;
#pragma unroll
    for (int i = 0; i < 4; i++)
        tile[ty + i * 8][tx] = w[(size_t)(d0 + ty + i * 8) * V_ + v0 + tx];
    __syncthreads();
#pragma unroll
    for (int i = 0; i < 4; i++) {
        size_t o = (size_t)(v0 + ty + i * 8) * D_ + d0 + tx;
        o16[o] = __float2half(tile[tx][ty + i * 8]);
    }
}

// ---------------------------------------------------------------------------
// LayerNorm statistics
// ---------------------------------------------------------------------------
__global__ void ln_stats_kernel(const float* __restrict__ x, float2* __restrict__ stats) {
    int row = blockIdx.x;
    float4 v = ((const float4*)(x + (size_t)row * D_))[threadIdx.x];
    float s = v.x + v.y + v.z + v.w;
    float q = v.x*v.x + v.y*v.y + v.z*v.z + v.w*v.w;
#pragma unroll
    for (int o = 16; o; o >>= 1) {
        s += __shfl_xor_sync(0xffffffffu, s, o);
        q += __shfl_xor_sync(0xffffffffu, q, o);
    }
    __shared__ float ss[8], sq[8];
    int w = threadIdx.x >> 5;
    if ((threadIdx.x & 31) == 0) { ss[w] = s; sq[w] = q; }
    __syncthreads();
    if (threadIdx.x == 0) {
        float S = 0.f, Q = 0.f;
#pragma unroll
        for (int i = 0; i < 8; i++) { S += ss[i]; Q += sq[i]; }
        float mu  = S / (float)D_;
        float var = Q / (float)D_ - mu * mu;
        stats[row] = make_float2(mu, rsqrtf(var + 1e-5f));
    }
}

// ---------------------------------------------------------------------------
// Apply LN while transposing (B,S,D)->(B,D,S)
// ---------------------------------------------------------------------------
__global__ void ln_transpose_kernel(const float* __restrict__ x,
                                    const float2* __restrict__ stats,
                                    const float* __restrict__ g,
                                    const float* __restrict__ bta,
                                    float* __restrict__ hT) {
    __shared__ float tile[32][33];
    int b  = blockIdx.z;
    int s0 = blockIdx.x * 32, d0 = blockIdx.y * 32;
    int tx = threadIdx.x, ty = threadIdx.y;
    float gg = g[d0 + tx], bb = bta[d0 + tx];
#pragma unroll
    for (int i = 0; i < 4; i++) {
        int s = s0 + ty + i * 8;
        float2 st = stats[b * S_ + s];
        float v = x[((size_t)(b * S_ + s)) * D_ + d0 + tx];
        tile[ty + i * 8][tx] = (v - st.x) * st.y * gg + bb;
    }
    __syncthreads();
#pragma unroll
    for (int i = 0; i < 4; i++) {
        int d = d0 + ty + i * 8;
        hT[((size_t)(b * D_ + d)) * S_ + s0 + tx] = tile[tx][ty + i * 8];
    }
}

// ---------------------------------------------------------------------------
// Final LN apply -> fp16
// ---------------------------------------------------------------------------
__global__ void apply_ln_kernel(const float* __restrict__ x,
                                const float2* __restrict__ stats,
                                const float* __restrict__ g,
                                const float* __restrict__ b,
                                __half* __restrict__ o16) {
    int row = blockIdx.x;
    int d0 = threadIdx.x * 4;
    float2 st = stats[row];
    float4 v  = *(const float4*)(x + (size_t)row * D_ + d0);
    float4 gg = *(const float4*)(g + d0);
    float4 bb = *(const float4*)(b + d0);
    __half2 p0 = __floats2half2_rn((v.x - st.x) * st.y * gg.x + bb.x,
                                   (v.y - st.x) * st.y * gg.y + bb.y);
    __half2 p1 = __floats2half2_rn((v.z - st.x) * st.y * gg.z + bb.z,
                                   (v.w - st.x) * st.y * gg.w + bb.w);
    uint2 packed = {*(uint32_t*)&p0, *(uint32_t*)&p1};
    *(uint2*)(o16 + (size_t)row * D_ + d0) = packed;
}

// ---------------------------------------------------------------------------
// Depthwise conv chain per (b,d) channel -> fp16 (B,D,S) output.
// ---------------------------------------------------------------------------
__global__ void __launch_bounds__(256) conv_kernel(const float* __restrict__ hT,
                                                   const float* __restrict__ lw,
                                                   const float* __restrict__ fw,
                                                   const float* __restrict__ mw,
                                                   __half* __restrict__ yT16) {
    int bd = blockIdx.x;
    int d  = bd & (D_ - 1);
    __shared__ float bufA[S_ + 64];
    __shared__ float bufB[S_ + 64];
    __shared__ float w3[3], wA[64], wB[64];
    int tid = threadIdx.x;
    if (tid < 64) {
        wA[tid] = fw[(size_t)d * 64 + tid];
        wB[tid] = fw[(size_t)(D_ + d) * 64 + tid];
    }
    if (tid < 3) w3[tid] = lw[d * 3 + tid];
    if (tid < 32) {
        bufA[tid] = 0.f; bufA[S_ + 32 + tid] = 0.f;
        bufB[tid] = 0.f; bufB[S_ + 32 + tid] = 0.f;
    }
    const float* cin = hT + (size_t)bd * S_;
    for (int i = tid; i < S_ / 4; i += 256)
        ((float4*)(bufA + 32))[i] = ((const float4*)cin)[i];
    __syncthreads();
    for (int s = tid; s < S_; s += 256)
        bufB[32 + s] = bufA[31 + s] * w3[0] + bufA[32 + s] * w3[1] + bufA[33 + s] * w3[2];
    __syncthreads();

    int s0 = tid * 8;
    float acc[8], win[8], nxt[8];

#pragma unroll
    for (int j = 0; j < 8; j++) { acc[j] = bufA[32 + s0 + j]; win[j] = bufB[s0 + j]; }
#pragma unroll
    for (int k0 = 0; k0 < 64; k0 += 8) {
#pragma unroll
        for (int j = 0; j < 8; j++) nxt[j] = bufB[s0 + 8 + k0 + j];
#pragma unroll
        for (int kk = 0; kk < 8; kk++) {
            float wk = wA[k0 + kk];
#pragma unroll
            for (int j = 0; j < 8; j++) {
                int ix = j + kk;
                acc[j] += (ix < 8 ? win[ix] : nxt[ix - 8]) * wk;
            }
        }
#pragma unroll
        for (int j = 0; j < 8; j++) win[j] = nxt[j];
    }
    __syncthreads();
#pragma unroll
    for (int j = 0; j < 8; j++) bufA[32 + s0 + j] = acc[j];
    __syncthreads();

    float mwd = mw[d];
#pragma unroll
    for (int j = 0; j < 8; j++) { acc[j] = 0.f; win[j] = bufA[s0 + j]; }
#pragma unroll
    for (int k0 = 0; k0 < 64; k0 += 8) {
#pragma unroll
        for (int j = 0; j < 8; j++) nxt[j] = bufA[s0 + 8 + k0 + j];
#pragma unroll
        for (int kk = 0; kk < 8; kk++) {
            float wk = wB[k0 + kk];
#pragma unroll
            for (int j = 0; j < 8; j++) {
                int ix = j + kk;
                acc[j] += (ix < 8 ? win[ix] : nxt[ix - 8]) * wk;
            }
        }
#pragma unroll
        for (int j = 0; j < 8; j++) win[j] = nxt[j];
    }
    __half hv[8];
#pragma unroll
    for (int j = 0; j < 8; j++) {
        float m = acc[j] * mwd;
        hv[j] = __float2half(m / (1.0f + expf(-m)));
    }
    *(uint4*)(yT16 + (size_t)bd * S_ + s0) = *(uint4*)hv;
}

// ---------------------------------------------------------------------------
// Host orchestration
// ---------------------------------------------------------------------------
static void* sym_addr(const void* sym) {
    void* p = nullptr;
    cudaGetSymbolAddress(&p, sym);
    return p;
}

extern "C" void kernel_launch(void* const* d_in, const int* in_sizes, int n_in,
                              void* d_out, int out_size) {
    (void)in_sizes; (void)n_in; (void)out_size;
    const int*   ids   = (const int*)d_in[0];
    const float* emb   = (const float*)d_in[1];
    const float* lw    = (const float*)d_in[2];
    const float* fw    = (const float*)d_in[3];
    const float* mw    = (const float*)d_in[4];
    const float* ln1g  = (const float*)d_in[5];
    const float* ln1b  = (const float*)d_in[6];
    const float* refW  = (const float*)d_in[7];
    const float* refb  = (const float*)d_in[8];
    const float* gateW = (const float*)d_in[9];
    const float* gateb = (const float*)d_in[10];
    const float* lnfg  = (const float*)d_in[11];
    const float* lnfb  = (const float*)d_in[12];
    const float* outW  = (const float*)d_in[13];
    const float* outb  = (const float*)d_in[14];
    float* out = (float*)d_out;

    float*  x0  = (float*)sym_addr(g_x0);
    float*  x1  = (float*)sym_addr(g_x1);
    float*  hT  = (float*)sym_addr(g_hT);
    float*  rf  = (float*)sym_addr(g_ref);
    float2* st  = (float2*)sym_addr(g_stats);
    __half* x016 = (__half*)sym_addr(g_x016);
    __half* x116 = (__half*)sym_addr(g_x116);
    __half* yT16 = (__half*)sym_addr(g_yT16);
    __half* wr16 = (__half*)sym_addr(g_wr16);
    __half* wg16 = (__half*)sym_addr(g_wg16);
    __half* xf16 = (__half*)sym_addr(g_xf16);
    __half* wo16 = (__half*)sym_addr(g_wo16);

    cudaFuncSetAttribute(gemm_ref,    cudaFuncAttributeMaxDynamicSharedMemorySize, RGEMM_SMEM);
    cudaFuncSetAttribute(gemm_1p<0>,  cudaFuncAttributeMaxDynamicSharedMemorySize, OGEMM_SMEM);
    cudaFuncSetAttribute(gemm_1p<1>,  cudaFuncAttributeMaxDynamicSharedMemorySize, OGEMM_SMEM);

    {
        int n4 = NL_ * D_ * D_ / 4;
        conv16_kernel<<<(n4 + 255) / 256, 256>>>(refW,  wr16, n4);
        conv16_kernel<<<(n4 + 255) / 256, 256>>>(gateW, wg16, n4);
        wout_t16_kernel<<<dim3(V_ / 32, D_ / 32), dim3(32, 8)>>>(outW, wo16);
    }

    embed_kernel<<<M_, 256>>>(ids, emb, x0, x016);

    float* cur = x0;        float* nxt = x1;
    __half *cur16 = x016, *nxt16 = x116;
    for (int l = 0; l < NL_; l++) {
        ln_stats_kernel<<<M_, 256>>>(cur, st);
        ln_transpose_kernel<<<dim3(S_/32, D_/32, B_), dim3(32, 8)>>>(
            cur, st, ln1g + (size_t)l * D_, ln1b + (size_t)l * D_, hT);
        conv_kernel<<<B_*D_, 256>>>(
            hT, lw + (size_t)l * D_ * 3, fw + (size_t)l * 2 * D_ * 64,
            mw + (size_t)l * D_, yT16);
        gemm_ref<<<dim3(M_/128, D_/128), 256, RGEMM_SMEM>>>(
            yT16, wr16 + (size_t)l * D_ * D_,
            refb + (size_t)l * D_, rf, D_, D_);
        gemm_1p<1><<<dim3(M_/128, D_/128), 256, OGEMM_SMEM>>>(
            cur16, wg16 + (size_t)l * D_ * D_,
            gateb + (size_t)l * D_, rf, cur, nxt, nxt16,
            M_, D_, D_);
        { float* tf = cur; cur = nxt; nxt = tf; }
        { __half* th = cur16; cur16 = nxt16; nxt16 = th; }
    }

    ln_stats_kernel<<<M_, 256>>>(cur, st);
    apply_ln_kernel<<<M_, 256>>>(cur, st, lnfg, lnfb, xf16);
    gemm_1p<0><<<dim3(M_/128, V_/128), 256, OGEMM_SMEM>>>(
        xf16, wo16, outb, nullptr, nullptr, out, nullptr, M_, V_, D_);
}

// round 16
// speedup vs baseline: 1.1427x; 1.0011x over previous
#include <cuda_runtime.h>
#include <cuda_fp16.h>
#include <math.h>
#include <stdint.h>

#define B_  2
#define S_  2048
#define D_  1024
#define V_  32000
#define NL_ 6
#define M_  (B_*S_)   // 4096 tokens

// ---------------------------------------------------------------------------
// Scratch
// ---------------------------------------------------------------------------
__device__ float  g_x0[M_*D_];
__device__ float  g_x1[M_*D_];
__device__ float  g_ref[M_*D_];
__device__ float2 g_stats[M_];

__device__ __half g_hT16[M_*D_];                       // LN output, (B,D,S) fp16
__device__ __half g_x016[M_*D_], g_x116[M_*D_];
__device__ __half g_yT16[M_*D_];                       // conv out, (B,D,S) fp16
__device__ __half g_wr16[NL_*D_*D_];
__device__ __half g_wg16[NL_*D_*D_];
__device__ __half g_xf16[M_*D_];
__device__ __half g_wo16[(size_t)V_*D_];

// ---------------------------------------------------------------------------
// PTX helpers
// ---------------------------------------------------------------------------
__device__ __forceinline__ uint32_t smem_u32(const void* p) {
    uint32_t a;
    asm("{ .reg .u64 t; cvta.to.shared.u64 t, %1; cvt.u32.u64 %0, t; }" : "=r"(a) : "l"(p));
    return a;
}
__device__ __forceinline__ void cp16s(uint32_t saddr, const void* g) {
    asm volatile("cp.async.cg.shared.global [%0], [%1], 16;\n" :: "r"(saddr), "l"(g));
}
__device__ __forceinline__ void cp_commit() {
    asm volatile("cp.async.commit_group;\n" ::: "memory");
}
template<int N_> __device__ __forceinline__ void cp_wait() {
    asm volatile("cp.async.wait_group %0;\n" :: "n"(N_) : "memory");
}
__device__ __forceinline__ void mma_fp16(float* c, const uint32_t* a, const uint32_t* b) {
    asm volatile(
        "mma.sync.aligned.m16n8k16.row.col.f32.f16.f16.f32 "
        "{%0,%1,%2,%3}, {%4,%5,%6,%7}, {%8,%9}, {%0,%1,%2,%3};"
        : "+f"(c[0]), "+f"(c[1]), "+f"(c[2]), "+f"(c[3])
        : "r"(a[0]), "r"(a[1]), "r"(a[2]), "r"(a[3]), "r"(b[0]), "r"(b[1]));
}
#define LDSM4(r0, r1, r2, r3, addr) \
    asm volatile("ldmatrix.sync.aligned.m8n8.x4.shared.b16 {%0,%1,%2,%3}, [%4];" \
        : "=r"(r0), "=r"(r1), "=r"(r2), "=r"(r3) : "r"(addr))
#define LDSM4T(r0, r1, r2, r3, addr) \
    asm volatile("ldmatrix.sync.aligned.m8n8.x4.trans.shared.b16 {%0,%1,%2,%3}, [%4];" \
        : "=r"(r0), "=r"(r1), "=r"(r2), "=r"(r3) : "r"(addr))

// BK = 32. Token-major tile rows hold 32 fp16 = 64B, padded to 80B.
#define RSTR2   80
#define TILE2_B (128 * RSTR2)        // 10240 B per 128x32 fp16 tile

// ---------------------------------------------------------------------------
// Refine GEMM: A = yT16 (B,D,S) channel-major fp16 (ldmatrix.trans),
// B single fp16:  C = A*B + bias  (fp32 accum).
// CTA 128x128, BK=32, 8 warps (64x32), 3-stage cp.async pipeline.
// ---------------------------------------------------------------------------
#define ARSTR    272
#define ATILE2_B (32 * ARSTR)                // 8704 B
#define RSTAGE_B (ATILE2_B + TILE2_B)        // 18944 B
#define RGEMM_SMEM (3 * RSTAGE_B)            // 56832 B

__global__ void __launch_bounds__(256, 2) gemm_ref(
        const __half* __restrict__ AT,       // (B,D,S) fp16
        const __half* __restrict__ Bm,
        const float* __restrict__ bias,
        float* __restrict__ C, int N, int K)
{
    extern __shared__ char smem[];
    uint32_t sb = smem_u32(smem);

    int tid  = threadIdx.x;
    int lane = tid & 31;
    int warp = tid >> 5;
    int g = lane >> 2, t = lane & 3;
    int wm = (warp >> 2) * 64;
    int wn = (warp & 3) * 32;
    int m0 = blockIdx.x * 128, n0 = blockIdx.y * 128;
    int bz = m0 / S_;
    int sm0 = m0 & (S_ - 1);

    uint32_t aoffT = (uint32_t)((((lane & 7) + ((lane >> 4) & 1) * 8) * ARSTR) + ((lane >> 3) & 1) * 16);
    uint32_t boff  = (uint32_t)((((lane & 7) + ((lane >> 4) & 1) * 8) * RSTR2) + ((lane >> 3) & 1) * 16);

    float acc[4][4][4];
#pragma unroll
    for (int mi = 0; mi < 4; mi++)
#pragma unroll
        for (int ni = 0; ni < 4; ni++)
#pragma unroll
            for (int r = 0; r < 4; r++) acc[mi][ni][r] = 0.f;

    auto load_stage = [&](int st, int kt) {
        int k0 = kt * 32;
        uint32_t base = sb + (uint32_t)st * RSTAGE_B;
#pragma unroll
        for (int i = 0; i < 2; i++) {
            int id = tid + i * 256;
            int r = id >> 4, c = id & 15;
            cp16s(base + (uint32_t)(r * ARSTR + c * 16),
                  AT + (size_t)(bz * D_ + k0 + r) * S_ + sm0 + c * 8);
            int br = id >> 2, bc = id & 3;
            cp16s(base + ATILE2_B + (uint32_t)(br * RSTR2 + bc * 16),
                  Bm + (size_t)(n0 + br) * K + k0 + bc * 8);
        }
    };

    int KT = K >> 5;
    load_stage(0, 0); cp_commit();
    load_stage(1, 1); cp_commit();

    for (int kt = 0; kt < KT; kt++) {
        if (kt == KT - 1) cp_wait<0>(); else cp_wait<1>();
        __syncthreads();
        if (kt + 2 < KT) { load_stage((kt + 2) % 3, kt + 2); cp_commit(); }

        uint32_t base = sb + (uint32_t)(kt % 3) * RSTAGE_B;
        uint32_t tA = base, tB = base + ATILE2_B;

#pragma unroll
        for (int ks = 0; ks < 2; ks++) {
            uint32_t af[16], bf[8];
            uint32_t bks = tB + (uint32_t)(ks * 32);
            LDSM4(bf[0], bf[1], bf[2], bf[3], bks + (uint32_t)(wn * RSTR2) + boff);
            LDSM4(bf[4], bf[5], bf[6], bf[7], bks + (uint32_t)((wn + 16) * RSTR2) + boff);
            uint32_t aks = tA + (uint32_t)(ks * 16 * ARSTR);
#pragma unroll
            for (int mi = 0; mi < 4; mi++)
                LDSM4T(af[mi*4], af[mi*4+1], af[mi*4+2], af[mi*4+3],
                       aks + aoffT + (uint32_t)((wm + mi * 16) * 2));
#pragma unroll
            for (int mi = 0; mi < 4; mi++)
#pragma unroll
                for (int ni = 0; ni < 4; ni++)
                    mma_fp16(acc[mi][ni], &af[mi*4], &bf[ni*2]);
        }
    }

#pragma unroll
    for (int mi = 0; mi < 4; mi++) {
        int r0 = m0 + wm + mi * 16 + g;
#pragma unroll
        for (int ni = 0; ni < 4; ni++) {
            int c0 = n0 + wn + ni * 8 + t * 2;
            float bv0 = bias[c0], bv1 = bias[c0 + 1];
            size_t o0 = (size_t)r0 * N + c0;
            size_t o1 = (size_t)(r0 + 8) * N + c0;
            float* a4 = acc[mi][ni];
            C[o0]     = a4[0] + bv0;
            C[o0 + 1] = a4[1] + bv1;
            C[o1]     = a4[2] + bv0;
            C[o1 + 1] = a4[3] + bv1;
        }
    }
}

// ---------------------------------------------------------------------------
// Single-product fp16 GEMM (gate + output projection), token-major A, BK=32.
// EPI 0 (output): C = acc + bias (fp32)
// EPI 1 (gate)  : s=sigmoid(acc+bias); x' = s*refined+(1-s)*orig -> fp32+fp16
// ---------------------------------------------------------------------------
#define OSTAGE_B (2 * TILE2_B)         // 20480 B
#define OGEMM_SMEM (3 * OSTAGE_B)      // 61440 B

template<int EPI>
__global__ void __launch_bounds__(256, 2) gemm_1p(
        const __half* __restrict__ A, const __half* __restrict__ Bm,
        const float* __restrict__ bias,
        const float* __restrict__ refined, const float* __restrict__ orig,
        float* __restrict__ C, __half* __restrict__ C16,
        int M, int N, int K)
{
    extern __shared__ char smem[];
    uint32_t sb = smem_u32(smem);

    int tid  = threadIdx.x;
    int lane = tid & 31;
    int warp = tid >> 5;
    int g = lane >> 2, t = lane & 3;
    int wm = (warp >> 2) * 64;
    int wn = (warp & 3) * 32;
    int m0 = blockIdx.x * 128, n0 = blockIdx.y * 128;

    uint32_t aoff = (uint32_t)((((lane & 7) + ((lane >> 3) & 1) * 8) * RSTR2) + ((lane >> 4) & 1) * 16);
    uint32_t boff = (uint32_t)((((lane & 7) + ((lane >> 4) & 1) * 8) * RSTR2) + ((lane >> 3) & 1) * 16);

    float acc[4][4][4];
#pragma unroll
    for (int mi = 0; mi < 4; mi++)
#pragma unroll
        for (int ni = 0; ni < 4; ni++)
#pragma unroll
            for (int r = 0; r < 4; r++) acc[mi][ni][r] = 0.f;

    auto load_stage = [&](int st, int kt) {
        int k0 = kt * 32;
        uint32_t base = sb + (uint32_t)st * OSTAGE_B;
#pragma unroll
        for (int i = 0; i < 2; i++) {
            int id = tid + i * 256;
            int r = id >> 2, c = id & 3;
            uint32_t so = (uint32_t)(r * RSTR2 + c * 16);
            cp16s(base + so,           A  + (size_t)(m0 + r) * K + k0 + c * 8);
            cp16s(base + TILE2_B + so, Bm + (size_t)(n0 + r) * K + k0 + c * 8);
        }
    };

    int KT = K >> 5;
    load_stage(0, 0); cp_commit();
    load_stage(1, 1); cp_commit();

    for (int kt = 0; kt < KT; kt++) {
        if (kt == KT - 1) cp_wait<0>(); else cp_wait<1>();
        __syncthreads();
        if (kt + 2 < KT) { load_stage((kt + 2) % 3, kt + 2); cp_commit(); }

        uint32_t base = sb + (uint32_t)(kt % 3) * OSTAGE_B;
        uint32_t tA = base, tB = base + TILE2_B;

#pragma unroll
        for (int ks = 0; ks < 2; ks++) {
            uint32_t af[16], bf[8];
            uint32_t bks = tB + (uint32_t)(ks * 32);
            uint32_t aks = tA + (uint32_t)(ks * 32);
            LDSM4(bf[0], bf[1], bf[2], bf[3], bks + (uint32_t)(wn * RSTR2) + boff);
            LDSM4(bf[4], bf[5], bf[6], bf[7], bks + (uint32_t)((wn + 16) * RSTR2) + boff);
#pragma unroll
            for (int mi = 0; mi < 4; mi++)
                LDSM4(af[mi*4], af[mi*4+1], af[mi*4+2], af[mi*4+3],
                      aks + (uint32_t)((wm + mi * 16) * RSTR2) + aoff);
#pragma unroll
            for (int mi = 0; mi < 4; mi++)
#pragma unroll
                for (int ni = 0; ni < 4; ni++)
                    mma_fp16(acc[mi][ni], &af[mi*4], &bf[ni*2]);
        }
    }

#pragma unroll
    for (int mi = 0; mi < 4; mi++) {
        int r0 = m0 + wm + mi * 16 + g;
#pragma unroll
        for (int ni = 0; ni < 4; ni++) {
            int c0 = n0 + wn + ni * 8 + t * 2;
            float bv0 = bias[c0], bv1 = bias[c0 + 1];
            size_t o0 = (size_t)r0 * N + c0;
            size_t o1 = (size_t)(r0 + 8) * N + c0;
            float* a4 = acc[mi][ni];
            if (EPI == 0) {
                C[o0]     = a4[0] + bv0;
                C[o0 + 1] = a4[1] + bv1;
                C[o1]     = a4[2] + bv0;
                C[o1 + 1] = a4[3] + bv1;
            } else {
                float pre[4] = {a4[0] + bv0, a4[1] + bv1, a4[2] + bv0, a4[3] + bv1};
                size_t offs[4] = {o0, o0 + 1, o1, o1 + 1};
#pragma unroll
                for (int j = 0; j < 4; j++) {
                    float gt = 1.f / (1.f + expf(-pre[j]));
                    float res = gt * refined[offs[j]] + (1.f - gt) * orig[offs[j]];
                    C[offs[j]] = res;
                    C16[offs[j]] = __float2half(res);
                }
            }
        }
    }
}

// ---------------------------------------------------------------------------
// Embedding + sinusoidal PE (+ fp16 copy for layer-0 gate A)
// ---------------------------------------------------------------------------
__global__ void embed_kernel(const int* __restrict__ ids,
                             const float* __restrict__ emb,
                             float* __restrict__ x,
                             __half* __restrict__ x16) {
    int row = blockIdx.x;
    int s   = row & (S_ - 1);
    int tok = ids[row];
    int d0  = threadIdx.x * 4;
    float4 e = *(const float4*)(emb + (size_t)tok * D_ + d0);
    const float cln = -logf(10000.0f) / (float)D_;
    float pe[4];
#pragma unroll
    for (int j = 0; j < 4; j += 2) {
        float freq = expf(cln * (float)(d0 + j));
        float a = (float)s * freq;
        pe[j]   = sinf(a);
        pe[j+1] = cosf(a);
    }
    float o[4] = {e.x + pe[0], e.y + pe[1], e.z + pe[2], e.w + pe[3]};
    *(float4*)(x + (size_t)row * D_ + d0) = *(float4*)o;
    __half2 p0 = __floats2half2_rn(o[0], o[1]);
    __half2 p1 = __floats2half2_rn(o[2], o[3]);
    uint2 packed = {*(uint32_t*)&p0, *(uint32_t*)&p1};
    *(uint2*)(x16 + (size_t)row * D_ + d0) = packed;
}

// ---------------------------------------------------------------------------
// fp16 convert (layer weights)
// ---------------------------------------------------------------------------
__global__ void conv16_kernel(const float* __restrict__ w,
                              __half* __restrict__ o, int n4) {
    int i = blockIdx.x * 256 + threadIdx.x;
    if (i >= n4) return;
    float4 v = ((const float4*)w)[i];
    __half2 p0 = __floats2half2_rn(v.x, v.y);
    __half2 p1 = __floats2half2_rn(v.z, v.w);
    uint2 packed = {*(uint32_t*)&p0, *(uint32_t*)&p1};
    ((uint2*)o)[i] = packed;
}

// ---------------------------------------------------------------------------
// outW (D,V) -> [V][D] fp16
// ---------------------------------------------------------------------------
__global__ void wout_t16_kernel(const float* __restrict__ w,
                                __half* __restrict__ o16) {
    __shared__ float tile[32][33];
    int v0 = blockIdx.x * 32, d0 = blockIdx.y * 32;
    int tx = threadIdx.x, ty = threadIdx.y;
#pragma unroll
    for (int i = 0; i < 4; i++)
        tile[ty + i * 8][tx] = w[(size_t)(d0 + ty + i * 8) * V_ + v0 + tx];
    __syncthreads();
#pragma unroll
    for (int i = 0; i < 4; i++) {
        size_t o = (size_t)(v0 + ty + i * 8) * D_ + d0 + tx;
        o16[o] = __float2half(tile[tx][ty + i * 8]);
    }
}

// ---------------------------------------------------------------------------
// LayerNorm statistics
// ---------------------------------------------------------------------------
__global__ void ln_stats_kernel(const float* __restrict__ x, float2* __restrict__ stats) {
    int row = blockIdx.x;
    float4 v = ((const float4*)(x + (size_t)row * D_))[threadIdx.x];
    float s = v.x + v.y + v.z + v.w;
    float q = v.x*v.x + v.y*v.y + v.z*v.z + v.w*v.w;
#pragma unroll
    for (int o = 16; o; o >>= 1) {
        s += __shfl_xor_sync(0xffffffffu, s, o);
        q += __shfl_xor_sync(0xffffffffu, q, o);
    }
    __shared__ float ss[8], sq[8];
    int w = threadIdx.x >> 5;
    if ((threadIdx.x & 31) == 0) { ss[w] = s; sq[w] = q; }
    __syncthreads();
    if (threadIdx.x == 0) {
        float S = 0.f, Q = 0.f;
#pragma unroll
        for (int i = 0; i < 8; i++) { S += ss[i]; Q += sq[i]; }
        float mu  = S / (float)D_;
        float var = Q / (float)D_ - mu * mu;
        stats[row] = make_float2(mu, rsqrtf(var + 1e-5f));
    }
}

// ---------------------------------------------------------------------------
// Apply LN while transposing (B,S,D)->(B,D,S); fp16 output.
// ---------------------------------------------------------------------------
__global__ void ln_transpose_kernel(const float* __restrict__ x,
                                    const float2* __restrict__ stats,
                                    const float* __restrict__ g,
                                    const float* __restrict__ bta,
                                    __half* __restrict__ hT16) {
    __shared__ float tile[32][33];
    int b  = blockIdx.z;
    int s0 = blockIdx.x * 32, d0 = blockIdx.y * 32;
    int tx = threadIdx.x, ty = threadIdx.y;
    float gg = g[d0 + tx], bb = bta[d0 + tx];
#pragma unroll
    for (int i = 0; i < 4; i++) {
        int s = s0 + ty + i * 8;
        float2 st = stats[b * S_ + s];
        float v = x[((size_t)(b * S_ + s)) * D_ + d0 + tx];
        tile[ty + i * 8][tx] = (v - st.x) * st.y * gg + bb;
    }
    __syncthreads();
#pragma unroll
    for (int i = 0; i < 4; i++) {
        int d = d0 + ty + i * 8;
        hT16[((size_t)(b * D_ + d)) * S_ + s0 + tx] = __float2half(tile[tx][ty + i * 8]);
    }
}

// ---------------------------------------------------------------------------
// Final LN apply -> fp16
// ---------------------------------------------------------------------------
__global__ void apply_ln_kernel(const float* __restrict__ x,
                                const float2* __restrict__ stats,
                                const float* __restrict__ g,
                                const float* __restrict__ b,
                                __half* __restrict__ o16) {
    int row = blockIdx.x;
    int d0 = threadIdx.x * 4;
    float2 st = stats[row];
    float4 v  = *(const float4*)(x + (size_t)row * D_ + d0);
    float4 gg = *(const float4*)(g + d0);
    float4 bb = *(const float4*)(b + d0);
    __half2 p0 = __floats2half2_rn((v.x - st.x) * st.y * gg.x + bb.x,
                                   (v.y - st.x) * st.y * gg.y + bb.y);
    __half2 p1 = __floats2half2_rn((v.z - st.x) * st.y * gg.z + bb.z,
                                   (v.w - st.x) * st.y * gg.w + bb.w);
    uint2 packed = {*(uint32_t*)&p0, *(uint32_t*)&p1};
    *(uint2*)(o16 + (size_t)row * D_ + d0) = packed;
}

// ---------------------------------------------------------------------------
// Depthwise conv chain per (b,d) channel; fp16 in (B,D,S), fp16 out.
// Internals fp32.
// ---------------------------------------------------------------------------
__global__ void __launch_bounds__(256) conv_kernel(const __half* __restrict__ hT16,
                                                   const float* __restrict__ lw,
                                                   const float* __restrict__ fw,
                                                   const float* __restrict__ mw,
                                                   __half* __restrict__ yT16) {
    int bd = blockIdx.x;
    int d  = bd & (D_ - 1);
    __shared__ float bufA[S_ + 64];
    __shared__ float bufB[S_ + 64];
    __shared__ float w3[3], wA[64], wB[64];
    int tid = threadIdx.x;
    if (tid < 64) {
        wA[tid] = fw[(size_t)d * 64 + tid];
        wB[tid] = fw[(size_t)(D_ + d) * 64 + tid];
    }
    if (tid < 3) w3[tid] = lw[d * 3 + tid];
    if (tid < 32) {
        bufA[tid] = 0.f; bufA[S_ + 32 + tid] = 0.f;
        bufB[tid] = 0.f; bufB[S_ + 32 + tid] = 0.f;
    }
    const __half* cin = hT16 + (size_t)bd * S_;
    for (int i = tid; i < S_ / 8; i += 256) {
        uint4 raw = ((const uint4*)cin)[i];
        __half2* hp = (__half2*)&raw;
        float* dst = bufA + 32 + i * 8;
#pragma unroll
        for (int j = 0; j < 4; j++) {
            float2 f = __half22float2(hp[j]);
            dst[j * 2]     = f.x;
            dst[j * 2 + 1] = f.y;
        }
    }
    __syncthreads();
    for (int s = tid; s < S_; s += 256)
        bufB[32 + s] = bufA[31 + s] * w3[0] + bufA[32 + s] * w3[1] + bufA[33 + s] * w3[2];
    __syncthreads();

    int s0 = tid * 8;
    float acc[8], win[8], nxt[8];

#pragma unroll
    for (int j = 0; j < 8; j++) { acc[j] = bufA[32 + s0 + j]; win[j] = bufB[s0 + j]; }
#pragma unroll
    for (int k0 = 0; k0 < 64; k0 += 8) {
#pragma unroll
        for (int j = 0; j < 8; j++) nxt[j] = bufB[s0 + 8 + k0 + j];
#pragma unroll
        for (int kk = 0; kk < 8; kk++) {
            float wk = wA[k0 + kk];
#pragma unroll
            for (int j = 0; j < 8; j++) {
                int ix = j + kk;
                acc[j] += (ix < 8 ? win[ix] : nxt[ix - 8]) * wk;
            }
        }
#pragma unroll
        for (int j = 0; j < 8; j++) win[j] = nxt[j];
    }
    __syncthreads();
#pragma unroll
    for (int j = 0; j < 8; j++) bufA[32 + s0 + j] = acc[j];
    __syncthreads();

    float mwd = mw[d];
#pragma unroll
    for (int j = 0; j < 8; j++) { acc[j] = 0.f; win[j] = bufA[s0 + j]; }
#pragma unroll
    for (int k0 = 0; k0 < 64; k0 += 8) {
#pragma unroll
        for (int j = 0; j < 8; j++) nxt[j] = bufA[s0 + 8 + k0 + j];
#pragma unroll
        for (int kk = 0; kk < 8; kk++) {
            float wk = wB[k0 + kk];
#pragma unroll
            for (int j = 0; j < 8; j++) {
                int ix = j + kk;
                acc[j] += (ix < 8 ? win[ix] : nxt[ix - 8]) * wk;
            }
        }
#pragma unroll
        for (int j = 0; j < 8; j++) win[j] = nxt[j];
    }
    __half hv[8];
#pragma unroll
    for (int j = 0; j < 8; j++) {
        float m = acc[j] * mwd;
        hv[j] = __float2half(m / (1.0f + expf(-m)));
    }
    *(uint4*)(yT16 + (size_t)bd * S_ + s0) = *(uint4*)hv;
}

// ---------------------------------------------------------------------------
// Host orchestration
// ---------------------------------------------------------------------------
static void* sym_addr(const void* sym) {
    void* p = nullptr;
    cudaGetSymbolAddress(&p, sym);
    return p;
}

extern "C" void kernel_launch(void* const* d_in, const int* in_sizes, int n_in,
                              void* d_out, int out_size) {
    (void)in_sizes; (void)n_in; (void)out_size;
    const int*   ids   = (const int*)d_in[0];
    const float* emb   = (const float*)d_in[1];
    const float* lw    = (const float*)d_in[2];
    const float* fw    = (const float*)d_in[3];
    const float* mw    = (const float*)d_in[4];
    const float* ln1g  = (const float*)d_in[5];
    const float* ln1b  = (const float*)d_in[6];
    const float* refW  = (const float*)d_in[7];
    const float* refb  = (const float*)d_in[8];
    const float* gateW = (const float*)d_in[9];
    const float* gateb = (const float*)d_in[10];
    const float* lnfg  = (const float*)d_in[11];
    const float* lnfb  = (const float*)d_in[12];
    const float* outW  = (const float*)d_in[13];
    const float* outb  = (const float*)d_in[14];
    float* out = (float*)d_out;

    float*  x0  = (float*)sym_addr(g_x0);
    float*  x1  = (float*)sym_addr(g_x1);
    float*  rf  = (float*)sym_addr(g_ref);
    float2* st  = (float2*)sym_addr(g_stats);
    __half* hT16 = (__half*)sym_addr(g_hT16);
    __half* x016 = (__half*)sym_addr(g_x016);
    __half* x116 = (__half*)sym_addr(g_x116);
    __half* yT16 = (__half*)sym_addr(g_yT16);
    __half* wr16 = (__half*)sym_addr(g_wr16);
    __half* wg16 = (__half*)sym_addr(g_wg16);
    __half* xf16 = (__half*)sym_addr(g_xf16);
    __half* wo16 = (__half*)sym_addr(g_wo16);

    cudaFuncSetAttribute(gemm_ref,    cudaFuncAttributeMaxDynamicSharedMemorySize, RGEMM_SMEM);
    cudaFuncSetAttribute(gemm_1p<0>,  cudaFuncAttributeMaxDynamicSharedMemorySize, OGEMM_SMEM);
    cudaFuncSetAttribute(gemm_1p<1>,  cudaFuncAttributeMaxDynamicSharedMemorySize, OGEMM_SMEM);

    {
        int n4 = NL_ * D_ * D_ / 4;
        conv16_kernel<<<(n4 + 255) / 256, 256>>>(refW,  wr16, n4);
        conv16_kernel<<<(n4 + 255) / 256, 256>>>(gateW, wg16, n4);
        wout_t16_kernel<<<dim3(V_ / 32, D_ / 32), dim3(32, 8)>>>(outW, wo16);
    }

    embed_kernel<<<M_, 256>>>(ids, emb, x0, x016);

    float* cur = x0;        float* nxt = x1;
    __half *cur16 = x016, *nxt16 = x116;
    for (int l = 0; l < NL_; l++) {
        ln_stats_kernel<<<M_, 256>>>(cur, st);
        ln_transpose_kernel<<<dim3(S_/32, D_/32, B_), dim3(32, 8)>>>(
            cur, st, ln1g + (size_t)l * D_, ln1b + (size_t)l * D_, hT16);
        conv_kernel<<<B_*D_, 256>>>(
            hT16, lw + (size_t)l * D_ * 3, fw + (size_t)l * 2 * D_ * 64,
            mw + (size_t)l * D_, yT16);
        gemm_ref<<<dim3(M_/128, D_/128), 256, RGEMM_SMEM>>>(
            yT16, wr16 + (size_t)l * D_ * D_,
            refb + (size_t)l * D_, rf, D_, D_);
        gemm_1p<1><<<dim3(M_/128, D_/128), 256, OGEMM_SMEM>>>(
            cur16, wg16 + (size_t)l * D_ * D_,
            gateb + (size_t)l * D_, rf, cur, nxt, nxt16,
            M_, D_, D_);
        { float* tf = cur; cur = nxt; nxt = tf; }
        { __half* th = cur16; cur16 = nxt16; nxt16 = th; }
    }

    ln_stats_kernel<<<M_, 256>>>(cur, st);
    apply_ln_kernel<<<M_, 256>>>(cur, st, lnfg, lnfb, xf16);
    gemm_1p<0><<<dim3(M_/128, V_/128), 256, OGEMM_SMEM>>>(
        xf16, wo16, outb, nullptr, nullptr, out, nullptr, M_, V_, D_);
}

// round 17
// speedup vs baseline: 1.1841x; 1.0362x over previous
#include <cuda_runtime.h>
#include <cuda_fp16.h>
#include <math.h>
#include <stdint.h>

#define B_  2
#define S_  2048
#define D_  1024
#define V_  32000
#define NL_ 6
#define M_  (B_*S_)   // 4096 tokens

// ---------------------------------------------------------------------------
// Scratch
// ---------------------------------------------------------------------------
__device__ float  g_x0[M_*D_];
__device__ float  g_x1[M_*D_];
__device__ float  g_ref[M_*D_];
__device__ float2 g_stats[M_];

__device__ __half g_hT16[M_*D_];                       // LN output, (B,D,S) fp16
__device__ __half g_x016[M_*D_], g_x116[M_*D_];
__device__ __half g_yT16[M_*D_];                       // conv out, (B,D,S) fp16
__device__ __half g_wr16[NL_*D_*D_];
__device__ __half g_wg16[NL_*D_*D_];
__device__ __half g_xf16[M_*D_];
__device__ __half g_wo16[(size_t)V_*D_];

// ---------------------------------------------------------------------------
// PTX helpers
// ---------------------------------------------------------------------------
__device__ __forceinline__ uint32_t smem_u32(const void* p) {
    uint32_t a;
    asm("{ .reg .u64 t; cvta.to.shared.u64 t, %1; cvt.u32.u64 %0, t; }" : "=r"(a) : "l"(p));
    return a;
}
__device__ __forceinline__ void cp16s(uint32_t saddr, const void* g) {
    asm volatile("cp.async.cg.shared.global [%0], [%1], 16;\n" :: "r"(saddr), "l"(g));
}
__device__ __forceinline__ void cp_commit() {
    asm volatile("cp.async.commit_group;\n" ::: "memory");
}
template<int N_> __device__ __forceinline__ void cp_wait() {
    asm volatile("cp.async.wait_group %0;\n" :: "n"(N_) : "memory");
}
__device__ __forceinline__ void mma_fp16(float* c, const uint32_t* a, const uint32_t* b) {
    asm volatile(
        "mma.sync.aligned.m16n8k16.row.col.f32.f16.f16.f32 "
        "{%0,%1,%2,%3}, {%4,%5,%6,%7}, {%8,%9}, {%0,%1,%2,%3};"
        : "+f"(c[0]), "+f"(c[1]), "+f"(c[2]), "+f"(c[3])
        : "r"(a[0]), "r"(a[1]), "r"(a[2]), "r"(a[3]), "r"(b[0]), "r"(b[1]));
}
#define LDSM4(r0, r1, r2, r3, addr) \
    asm volatile("ldmatrix.sync.aligned.m8n8.x4.shared.b16 {%0,%1,%2,%3}, [%4];" \
        : "=r"(r0), "=r"(r1), "=r"(r2), "=r"(r3) : "r"(addr))
#define LDSM4T(r0, r1, r2, r3, addr) \
    asm volatile("ldmatrix.sync.aligned.m8n8.x4.trans.shared.b16 {%0,%1,%2,%3}, [%4];" \
        : "=r"(r0), "=r"(r1), "=r"(r2), "=r"(r3) : "r"(addr))

// BK = 64. Token-major tile rows hold 64 fp16 = 128B, padded to 144B
// (odd multiple of 16 -> contiguous-128B phases, conflict-free).
#define RSTR3   144
#define TILE3_B (128 * RSTR3)        // 18432 B per 128x64 fp16 tile

// ---------------------------------------------------------------------------
// Refine GEMM: A = yT16 (B,D,S) channel-major fp16 (ldmatrix.trans),
// B single fp16:  C = A*B + bias  (fp32 accum).
// CTA 128x128, BK=64, 8 warps (64x32), 3-stage cp.async pipeline.
// A^T smem tile: 64 k-rows x 256B, stride 272B.
// ---------------------------------------------------------------------------
#define ARSTR    272
#define ATILE3_B (64 * ARSTR)                // 17408 B
#define RSTAGE_B (ATILE3_B + TILE3_B)        // 35840 B
#define RGEMM_SMEM (3 * RSTAGE_B)            // 107520 B

__global__ void __launch_bounds__(256, 2) gemm_ref(
        const __half* __restrict__ AT,       // (B,D,S) fp16
        const __half* __restrict__ Bm,
        const float* __restrict__ bias,
        float* __restrict__ C, int N, int K)
{
    extern __shared__ char smem[];
    uint32_t sb = smem_u32(smem);

    int tid  = threadIdx.x;
    int lane = tid & 31;
    int warp = tid >> 5;
    int g = lane >> 2, t = lane & 3;
    int wm = (warp >> 2) * 64;
    int wn = (warp & 3) * 32;
    int m0 = blockIdx.x * 128, n0 = blockIdx.y * 128;
    int bz = m0 / S_;
    int sm0 = m0 & (S_ - 1);

    uint32_t aoffT = (uint32_t)((((lane & 7) + ((lane >> 4) & 1) * 8) * ARSTR) + ((lane >> 3) & 1) * 16);
    uint32_t boff  = (uint32_t)((((lane & 7) + ((lane >> 4) & 1) * 8) * RSTR3) + ((lane >> 3) & 1) * 16);

    float acc[4][4][4];
#pragma unroll
    for (int mi = 0; mi < 4; mi++)
#pragma unroll
        for (int ni = 0; ni < 4; ni++)
#pragma unroll
            for (int r = 0; r < 4; r++) acc[mi][ni][r] = 0.f;

    auto load_stage = [&](int st, int kt) {
        int k0 = kt * 64;
        uint32_t base = sb + (uint32_t)st * RSTAGE_B;
#pragma unroll
        for (int i = 0; i < 4; i++) {
            int id = tid + i * 256;
            // A^T: 64 k-rows x 16 chunks of 16B
            int r = id >> 4, c = id & 15;
            cp16s(base + (uint32_t)(r * ARSTR + c * 16),
                  AT + (size_t)(bz * D_ + k0 + r) * S_ + sm0 + c * 8);
            // B: 128 rows x 8 chunks of 16B
            int br = id >> 3, bc = id & 7;
            cp16s(base + ATILE3_B + (uint32_t)(br * RSTR3 + bc * 16),
                  Bm + (size_t)(n0 + br) * K + k0 + bc * 8);
        }
    };

    int KT = K >> 6;
    load_stage(0, 0); cp_commit();
    load_stage(1, 1); cp_commit();

    for (int kt = 0; kt < KT; kt++) {
        if (kt == KT - 1) cp_wait<0>(); else cp_wait<1>();
        __syncthreads();
        if (kt + 2 < KT) { load_stage((kt + 2) % 3, kt + 2); cp_commit(); }

        uint32_t base = sb + (uint32_t)(kt % 3) * RSTAGE_B;
        uint32_t tA = base, tB = base + ATILE3_B;

#pragma unroll
        for (int ks = 0; ks < 4; ks++) {
            uint32_t af[16], bf[8];
            uint32_t bks = tB + (uint32_t)(ks * 32);
            LDSM4(bf[0], bf[1], bf[2], bf[3], bks + (uint32_t)(wn * RSTR3) + boff);
            LDSM4(bf[4], bf[5], bf[6], bf[7], bks + (uint32_t)((wn + 16) * RSTR3) + boff);
            uint32_t aks = tA + (uint32_t)(ks * 16 * ARSTR);
#pragma unroll
            for (int mi = 0; mi < 4; mi++)
                LDSM4T(af[mi*4], af[mi*4+1], af[mi*4+2], af[mi*4+3],
                       aks + aoffT + (uint32_t)((wm + mi * 16) * 2));
#pragma unroll
            for (int mi = 0; mi < 4; mi++)
#pragma unroll
                for (int ni = 0; ni < 4; ni++)
                    mma_fp16(acc[mi][ni], &af[mi*4], &bf[ni*2]);
        }
    }

#pragma unroll
    for (int mi = 0; mi < 4; mi++) {
        int r0 = m0 + wm + mi * 16 + g;
#pragma unroll
        for (int ni = 0; ni < 4; ni++) {
            int c0 = n0 + wn + ni * 8 + t * 2;
            float bv0 = bias[c0], bv1 = bias[c0 + 1];
            size_t o0 = (size_t)r0 * N + c0;
            size_t o1 = (size_t)(r0 + 8) * N + c0;
            float* a4 = acc[mi][ni];
            C[o0]     = a4[0] + bv0;
            C[o0 + 1] = a4[1] + bv1;
            C[o1]     = a4[2] + bv0;
            C[o1 + 1] = a4[3] + bv1;
        }
    }
}

// ---------------------------------------------------------------------------
// Single-product fp16 GEMM (gate + output projection), token-major A, BK=64.
// EPI 0 (output): C = acc + bias (fp32)
// EPI 1 (gate)  : s=sigmoid(acc+bias); x' = s*refined+(1-s)*orig -> fp32+fp16
// ---------------------------------------------------------------------------
#define OSTAGE_B (2 * TILE3_B)         // 36864 B
#define OGEMM_SMEM (3 * OSTAGE_B)      // 110592 B

template<int EPI>
__global__ void __launch_bounds__(256, 2) gemm_1p(
        const __half* __restrict__ A, const __half* __restrict__ Bm,
        const float* __restrict__ bias,
        const float* __restrict__ refined, const float* __restrict__ orig,
        float* __restrict__ C, __half* __restrict__ C16,
        int M, int N, int K)
{
    extern __shared__ char smem[];
    uint32_t sb = smem_u32(smem);

    int tid  = threadIdx.x;
    int lane = tid & 31;
    int warp = tid >> 5;
    int g = lane >> 2, t = lane & 3;
    int wm = (warp >> 2) * 64;
    int wn = (warp & 3) * 32;
    int m0 = blockIdx.x * 128, n0 = blockIdx.y * 128;

    uint32_t aoff = (uint32_t)((((lane & 7) + ((lane >> 3) & 1) * 8) * RSTR3) + ((lane >> 4) & 1) * 16);
    uint32_t boff = (uint32_t)((((lane & 7) + ((lane >> 4) & 1) * 8) * RSTR3) + ((lane >> 3) & 1) * 16);

    float acc[4][4][4];
#pragma unroll
    for (int mi = 0; mi < 4; mi++)
#pragma unroll
        for (int ni = 0; ni < 4; ni++)
#pragma unroll
            for (int r = 0; r < 4; r++) acc[mi][ni][r] = 0.f;

    auto load_stage = [&](int st, int kt) {
        int k0 = kt * 64;
        uint32_t base = sb + (uint32_t)st * OSTAGE_B;
#pragma unroll
        for (int i = 0; i < 4; i++) {
            int id = tid + i * 256;
            int r = id >> 3, c = id & 7;
            uint32_t so = (uint32_t)(r * RSTR3 + c * 16);
            cp16s(base + so,           A  + (size_t)(m0 + r) * K + k0 + c * 8);
            cp16s(base + TILE3_B + so, Bm + (size_t)(n0 + r) * K + k0 + c * 8);
        }
    };

    int KT = K >> 6;
    load_stage(0, 0); cp_commit();
    load_stage(1, 1); cp_commit();

    for (int kt = 0; kt < KT; kt++) {
        if (kt == KT - 1) cp_wait<0>(); else cp_wait<1>();
        __syncthreads();
        if (kt + 2 < KT) { load_stage((kt + 2) % 3, kt + 2); cp_commit(); }

        uint32_t base = sb + (uint32_t)(kt % 3) * OSTAGE_B;
        uint32_t tA = base, tB = base + TILE3_B;

#pragma unroll
        for (int ks = 0; ks < 4; ks++) {
            uint32_t af[16], bf[8];
            uint32_t bks = tB + (uint32_t)(ks * 32);
            uint32_t aks = tA + (uint32_t)(ks * 32);
            LDSM4(bf[0], bf[1], bf[2], bf[3], bks + (uint32_t)(wn * RSTR3) + boff);
            LDSM4(bf[4], bf[5], bf[6], bf[7], bks + (uint32_t)((wn + 16) * RSTR3) + boff);
#pragma unroll
            for (int mi = 0; mi < 4; mi++)
                LDSM4(af[mi*4], af[mi*4+1], af[mi*4+2], af[mi*4+3],
                      aks + (uint32_t)((wm + mi * 16) * RSTR3) + aoff);
#pragma unroll
            for (int mi = 0; mi < 4; mi++)
#pragma unroll
                for (int ni = 0; ni < 4; ni++)
                    mma_fp16(acc[mi][ni], &af[mi*4], &bf[ni*2]);
        }
    }

#pragma unroll
    for (int mi = 0; mi < 4; mi++) {
        int r0 = m0 + wm + mi * 16 + g;
#pragma unroll
        for (int ni = 0; ni < 4; ni++) {
            int c0 = n0 + wn + ni * 8 + t * 2;
            float bv0 = bias[c0], bv1 = bias[c0 + 1];
            size_t o0 = (size_t)r0 * N + c0;
            size_t o1 = (size_t)(r0 + 8) * N + c0;
            float* a4 = acc[mi][ni];
            if (EPI == 0) {
                C[o0]     = a4[0] + bv0;
                C[o0 + 1] = a4[1] + bv1;
                C[o1]     = a4[2] + bv0;
                C[o1 + 1] = a4[3] + bv1;
            } else {
                float pre[4] = {a4[0] + bv0, a4[1] + bv1, a4[2] + bv0, a4[3] + bv1};
                size_t offs[4] = {o0, o0 + 1, o1, o1 + 1};
#pragma unroll
                for (int j = 0; j < 4; j++) {
                    float gt = 1.f / (1.f + expf(-pre[j]));
                    float res = gt * refined[offs[j]] + (1.f - gt) * orig[offs[j]];
                    C[offs[j]] = res;
                    C16[offs[j]] = __float2half(res);
                }
            }
        }
    }
}

// ---------------------------------------------------------------------------
// Embedding + sinusoidal PE (+ fp16 copy for layer-0 gate A)
// ---------------------------------------------------------------------------
__global__ void embed_kernel(const int* __restrict__ ids,
                             const float* __restrict__ emb,
                             float* __restrict__ x,
                             __half* __restrict__ x16) {
    int row = blockIdx.x;
    int s   = row & (S_ - 1);
    int tok = ids[row];
    int d0  = threadIdx.x * 4;
    float4 e = *(const float4*)(emb + (size_t)tok * D_ + d0);
    const float cln = -logf(10000.0f) / (float)D_;
    float pe[4];
#pragma unroll
    for (int j = 0; j < 4; j += 2) {
        float freq = expf(cln * (float)(d0 + j));
        float a = (float)s * freq;
        pe[j]   = sinf(a);
        pe[j+1] = cosf(a);
    }
    float o[4] = {e.x + pe[0], e.y + pe[1], e.z + pe[2], e.w + pe[3]};
    *(float4*)(x + (size_t)row * D_ + d0) = *(float4*)o;
    __half2 p0 = __floats2half2_rn(o[0], o[1]);
    __half2 p1 = __floats2half2_rn(o[2], o[3]);
    uint2 packed = {*(uint32_t*)&p0, *(uint32_t*)&p1};
    *(uint2*)(x16 + (size_t)row * D_ + d0) = packed;
}

// ---------------------------------------------------------------------------
// fp16 convert (layer weights)
// ---------------------------------------------------------------------------
__global__ void conv16_kernel(const float* __restrict__ w,
                              __half* __restrict__ o, int n4) {
    int i = blockIdx.x * 256 + threadIdx.x;
    if (i >= n4) return;
    float4 v = ((const float4*)w)[i];
    __half2 p0 = __floats2half2_rn(v.x, v.y);
    __half2 p1 = __floats2half2_rn(v.z, v.w);
    uint2 packed = {*(uint32_t*)&p0, *(uint32_t*)&p1};
    ((uint2*)o)[i] = packed;
}

// ---------------------------------------------------------------------------
// outW (D,V) -> [V][D] fp16
// ---------------------------------------------------------------------------
__global__ void wout_t16_kernel(const float* __restrict__ w,
                                __half* __restrict__ o16) {
    __shared__ float tile[32][33];
    int v0 = blockIdx.x * 32, d0 = blockIdx.y * 32;
    int tx = threadIdx.x, ty = threadIdx.y;
#pragma unroll
    for (int i = 0; i < 4; i++)
        tile[ty + i * 8][tx] = w[(size_t)(d0 + ty + i * 8) * V_ + v0 + tx];
    __syncthreads();
#pragma unroll
    for (int i = 0; i < 4; i++) {
        size_t o = (size_t)(v0 + ty + i * 8) * D_ + d0 + tx;
        o16[o] = __float2half(tile[tx][ty + i * 8]);
    }
}

// ---------------------------------------------------------------------------
// LayerNorm statistics
// ---------------------------------------------------------------------------
__global__ void ln_stats_kernel(const float* __restrict__ x, float2* __restrict__ stats) {
    int row = blockIdx.x;
    float4 v = ((const float4*)(x + (size_t)row * D_))[threadIdx.x];
    float s = v.x + v.y + v.z + v.w;
    float q = v.x*v.x + v.y*v.y + v.z*v.z + v.w*v.w;
#pragma unroll
    for (int o = 16; o; o >>= 1) {
        s += __shfl_xor_sync(0xffffffffu, s, o);
        q += __shfl_xor_sync(0xffffffffu, q, o);
    }
    __shared__ float ss[8], sq[8];
    int w = threadIdx.x >> 5;
    if ((threadIdx.x & 31) == 0) { ss[w] = s; sq[w] = q; }
    __syncthreads();
    if (threadIdx.x == 0) {
        float S = 0.f, Q = 0.f;
#pragma unroll
        for (int i = 0; i < 8; i++) { S += ss[i]; Q += sq[i]; }
        float mu  = S / (float)D_;
        float var = Q / (float)D_ - mu * mu;
        stats[row] = make_float2(mu, rsqrtf(var + 1e-5f));
    }
}

// ---------------------------------------------------------------------------
// Apply LN while transposing (B,S,D)->(B,D,S); fp16 output.
// ---------------------------------------------------------------------------
__global__ void ln_transpose_kernel(const float* __restrict__ x,
                                    const float2* __restrict__ stats,
                                    const float* __restrict__ g,
                                    const float* __restrict__ bta,
                                    __half* __restrict__ hT16) {
    __shared__ float tile[32][33];
    int b  = blockIdx.z;
    int s0 = blockIdx.x * 32, d0 = blockIdx.y * 32;
    int tx = threadIdx.x, ty = threadIdx.y;
    float gg = g[d0 + tx], bb = bta[d0 + tx];
#pragma unroll
    for (int i = 0; i < 4; i++) {
        int s = s0 + ty + i * 8;
        float2 st = stats[b * S_ + s];
        float v = x[((size_t)(b * S_ + s)) * D_ + d0 + tx];
        tile[ty + i * 8][tx] = (v - st.x) * st.y * gg + bb;
    }
    __syncthreads();
#pragma unroll
    for (int i = 0; i < 4; i++) {
        int d = d0 + ty + i * 8;
        hT16[((size_t)(b * D_ + d)) * S_ + s0 + tx] = __float2half(tile[tx][ty + i * 8]);
    }
}

// ---------------------------------------------------------------------------
// Final LN apply -> fp16
// ---------------------------------------------------------------------------
__global__ void apply_ln_kernel(const float* __restrict__ x,
                                const float2* __restrict__ stats,
                                const float* __restrict__ g,
                                const float* __restrict__ b,
                                __half* __restrict__ o16) {
    int row = blockIdx.x;
    int d0 = threadIdx.x * 4;
    float2 st = stats[row];
    float4 v  = *(const float4*)(x + (size_t)row * D_ + d0);
    float4 gg = *(const float4*)(g + d0);
    float4 bb = *(const float4*)(b + d0);
    __half2 p0 = __floats2half2_rn((v.x - st.x) * st.y * gg.x + bb.x,
                                   (v.y - st.x) * st.y * gg.y + bb.y);
    __half2 p1 = __floats2half2_rn((v.z - st.x) * st.y * gg.z + bb.z,
                                   (v.w - st.x) * st.y * gg.w + bb.w);
    uint2 packed = {*(uint32_t*)&p0, *(uint32_t*)&p1};
    *(uint2*)(o16 + (size_t)row * D_ + d0) = packed;
}

// ---------------------------------------------------------------------------
// Depthwise conv chain per (b,d) channel; fp16 in (B,D,S), fp16 out.
// Internals fp32.
// ---------------------------------------------------------------------------
__global__ void __launch_bounds__(256) conv_kernel(const __half* __restrict__ hT16,
                                                   const float* __restrict__ lw,
                                                   const float* __restrict__ fw,
                                                   const float* __restrict__ mw,
                                                   __half* __restrict__ yT16) {
    int bd = blockIdx.x;
    int d  = bd & (D_ - 1);
    __shared__ float bufA[S_ + 64];
    __shared__ float bufB[S_ + 64];
    __shared__ float w3[3], wA[64], wB[64];
    int tid = threadIdx.x;
    if (tid < 64) {
        wA[tid] = fw[(size_t)d * 64 + tid];
        wB[tid] = fw[(size_t)(D_ + d) * 64 + tid];
    }
    if (tid < 3) w3[tid] = lw[d * 3 + tid];
    if (tid < 32) {
        bufA[tid] = 0.f; bufA[S_ + 32 + tid] = 0.f;
        bufB[tid] = 0.f; bufB[S_ + 32 + tid] = 0.f;
    }
    const __half* cin = hT16 + (size_t)bd * S_;
    for (int i = tid; i < S_ / 8; i += 256) {
        uint4 raw = ((const uint4*)cin)[i];
        __half2* hp = (__half2*)&raw;
        float* dst = bufA + 32 + i * 8;
#pragma unroll
        for (int j = 0; j < 4; j++) {
            float2 f = __half22float2(hp[j]);
            dst[j * 2]     = f.x;
            dst[j * 2 + 1] = f.y;
        }
    }
    __syncthreads();
    for (int s = tid; s < S_; s += 256)
        bufB[32 + s] = bufA[31 + s] * w3[0] + bufA[32 + s] * w3[1] + bufA[33 + s] * w3[2];
    __syncthreads();

    int s0 = tid * 8;
    float acc[8], win[8], nxt[8];

#pragma unroll
    for (int j = 0; j < 8; j++) { acc[j] = bufA[32 + s0 + j]; win[j] = bufB[s0 + j]; }
#pragma unroll
    for (int k0 = 0; k0 < 64; k0 += 8) {
#pragma unroll
        for (int j = 0; j < 8; j++) nxt[j] = bufB[s0 + 8 + k0 + j];
#pragma unroll
        for (int kk = 0; kk < 8; kk++) {
            float wk = wA[k0 + kk];
#pragma unroll
            for (int j = 0; j < 8; j++) {
                int ix = j + kk;
                acc[j] += (ix < 8 ? win[ix] : nxt[ix - 8]) * wk;
            }
        }
#pragma unroll
        for (int j = 0; j < 8; j++) win[j] = nxt[j];
    }
    __syncthreads();
#pragma unroll
    for (int j = 0; j < 8; j++) bufA[32 + s0 + j] = acc[j];
    __syncthreads();

    float mwd = mw[d];
#pragma unroll
    for (int j = 0; j < 8; j++) { acc[j] = 0.f; win[j] = bufA[s0 + j]; }
#pragma unroll
    for (int k0 = 0; k0 < 64; k0 += 8) {
#pragma unroll
        for (int j = 0; j < 8; j++) nxt[j] = bufA[s0 + 8 + k0 + j];
#pragma unroll
        for (int kk = 0; kk < 8; kk++) {
            float wk = wB[k0 + kk];
#pragma unroll
            for (int j = 0; j < 8; j++) {
                int ix = j + kk;
                acc[j] += (ix < 8 ? win[ix] : nxt[ix - 8]) * wk;
            }
        }
#pragma unroll
        for (int j = 0; j < 8; j++) win[j] = nxt[j];
    }
    __half hv[8];
#pragma unroll
    for (int j = 0; j < 8; j++) {
        float m = acc[j] * mwd;
        hv[j] = __float2half(m / (1.0f + expf(-m)));
    }
    *(uint4*)(yT16 + (size_t)bd * S_ + s0) = *(uint4*)hv;
}

// ---------------------------------------------------------------------------
// Host orchestration
// ---------------------------------------------------------------------------
static void* sym_addr(const void* sym) {
    void* p = nullptr;
    cudaGetSymbolAddress(&p, sym);
    return p;
}

extern "C" void kernel_launch(void* const* d_in, const int* in_sizes, int n_in,
                              void* d_out, int out_size) {
    (void)in_sizes; (void)n_in; (void)out_size;
    const int*   ids   = (const int*)d_in[0];
    const float* emb   = (const float*)d_in[1];
    const float* lw    = (const float*)d_in[2];
    const float* fw    = (const float*)d_in[3];
    const float* mw    = (const float*)d_in[4];
    const float* ln1g  = (const float*)d_in[5];
    const float* ln1b  = (const float*)d_in[6];
    const float* refW  = (const float*)d_in[7];
    const float* refb  = (const float*)d_in[8];
    const float* gateW = (const float*)d_in[9];
    const float* gateb = (const float*)d_in[10];
    const float* lnfg  = (const float*)d_in[11];
    const float* lnfb  = (const float*)d_in[12];
    const float* outW  = (const float*)d_in[13];
    const float* outb  = (const float*)d_in[14];
    float* out = (float*)d_out;

    float*  x0  = (float*)sym_addr(g_x0);
    float*  x1  = (float*)sym_addr(g_x1);
    float*  rf  = (float*)sym_addr(g_ref);
    float2* st  = (float2*)sym_addr(g_stats);
    __half* hT16 = (__half*)sym_addr(g_hT16);
    __half* x016 = (__half*)sym_addr(g_x016);
    __half* x116 = (__half*)sym_addr(g_x116);
    __half* yT16 = (__half*)sym_addr(g_yT16);
    __half* wr16 = (__half*)sym_addr(g_wr16);
    __half* wg16 = (__half*)sym_addr(g_wg16);
    __half* xf16 = (__half*)sym_addr(g_xf16);
    __half* wo16 = (__half*)sym_addr(g_wo16);

    cudaFuncSetAttribute(gemm_ref,    cudaFuncAttributeMaxDynamicSharedMemorySize, RGEMM_SMEM);
    cudaFuncSetAttribute(gemm_1p<0>,  cudaFuncAttributeMaxDynamicSharedMemorySize, OGEMM_SMEM);
    cudaFuncSetAttribute(gemm_1p<1>,  cudaFuncAttributeMaxDynamicSharedMemorySize, OGEMM_SMEM);

    {
        int n4 = NL_ * D_ * D_ / 4;
        conv16_kernel<<<(n4 + 255) / 256, 256>>>(refW,  wr16, n4);
        conv16_kernel<<<(n4 + 255) / 256, 256>>>(gateW, wg16, n4);
        wout_t16_kernel<<<dim3(V_ / 32, D_ / 32), dim3(32, 8)>>>(outW, wo16);
    }

    embed_kernel<<<M_, 256>>>(ids, emb, x0, x016);

    float* cur = x0;        float* nxt = x1;
    __half *cur16 = x016, *nxt16 = x116;
    for (int l = 0; l < NL_; l++) {
        ln_stats_kernel<<<M_, 256>>>(cur, st);
        ln_transpose_kernel<<<dim3(S_/32, D_/32, B_), dim3(32, 8)>>>(
            cur, st, ln1g + (size_t)l * D_, ln1b + (size_t)l * D_, hT16);
        conv_kernel<<<B_*D_, 256>>>(
            hT16, lw + (size_t)l * D_ * 3, fw + (size_t)l * 2 * D_ * 64,
            mw + (size_t)l * D_, yT16);
        gemm_ref<<<dim3(M_/128, D_/128), 256, RGEMM_SMEM>>>(
            yT16, wr16 + (size_t)l * D_ * D_,
            refb + (size_t)l * D_, rf, D_, D_);
        gemm_1p<1><<<dim3(M_/128, D_/128), 256, OGEMM_SMEM>>>(
            cur16, wg16 + (size_t)l * D_ * D_,
            gateb + (size_t)l * D_, rf, cur, nxt, nxt16,
            M_, D_, D_);
        { float* tf = cur; cur = nxt; nxt = tf; }
        { __half* th = cur16; cur16 = nxt16; nxt16 = th; }
    }

    ln_stats_kernel<<<M_, 256>>>(cur, st);
    apply_ln_kernel<<<M_, 256>>>(cur, st, lnfg, lnfb, xf16);
    gemm_1p<0><<<dim3(M_/128, V_/128), 256, OGEMM_SMEM>>>(
        xf16, wo16, outb, nullptr, nullptr, out, nullptr, M_, V_, D_);
}